// round 1
// baseline (speedup 1.0000x reference)
#include <cuda_runtime.h>
#include <cstdint>

#define BATCH 4
#define T 1024
#define D 64
#define H 2
#define HD 32
#define DFF 256
#define NL 4
#define VOCAB 8192
#define BT (BATCH*T)

// ---------------- device scratch (no allocs allowed) ----------------
__device__ int8_t  g_x[BT*D];
__device__ int8_t  g_h[BT*D];
__device__ int8_t  g_q[BT*D];
__device__ int8_t  g_k[BT*D];
__device__ int8_t  g_v[BT*D];
__device__ int8_t  g_a[BT*D];
__device__ int8_t  g_u[BT*DFF];
__device__ int8_t  g_wq[NL*D*D], g_wk[NL*D*D], g_wv[NL*D*D], g_wo[NL*D*D];
__device__ int8_t  g_wup[NL*DFF*D], g_wdn[NL*D*DFF];
__device__ int     g_gattn[NL*D], g_gff[NL*D], g_gfin[D];
__device__ int8_t  g_ehi[VOCAB*D];
__device__ uint8_t g_elo[VOCAB*D];

// ---------------- helpers ----------------
__device__ __forceinline__ int wrap8(int v){ return (int)(signed char)(v & 0xff); }
__device__ __forceinline__ int clampi(int v,int lo,int hi){ return min(max(v,lo),hi); }
__device__ __forceinline__ int dp4a_su(int a, unsigned b, int c){
    int r; asm("dp4a.s32.u32 %0,%1,%2,%3;" : "=r"(r) : "r"(a),"r"(b),"r"(c)); return r;
}
__device__ __forceinline__ int gammaq(float w){
    float c = fminf(fmaxf(w,-2.f),2.f);
    float r = rintf(__fmul_rn(c,1024.f));
    return clampi((int)r,-32768,32767);
}

// ---------------- weight ternarization ----------------
__global__ void quant_weights(const float* qw, const float* kw, const float* vw,
                              const float* ow, const float* up, const float* dn){
    int m = blockIdx.x; const float* src; int8_t* dst; int n;
    if(m < 16){
        int l = m >> 2, wsel = m & 3; n = D*D;
        const float* bases[4] = {qw,kw,vw,ow};
        int8_t* dsts[4] = {g_wq,g_wk,g_wv,g_wo};
        src = bases[wsel] + l*n; dst = dsts[wsel] + l*n;
    } else if(m < 20){ int l=m-16; n=DFF*D; src=up+l*n; dst=g_wup+l*n; }
    else             { int l=m-20; n=D*DFF; src=dn+l*n; dst=g_wdn+l*n; }

    __shared__ float red[256];
    float s = 0.f;
    for(int i=threadIdx.x;i<n;i+=256) s += fabsf(src[i]);
    red[threadIdx.x]=s; __syncthreads();
    for(int o=128;o>0;o>>=1){ if(threadIdx.x<o) red[threadIdx.x]+=red[threadIdx.x+o]; __syncthreads(); }
    float scale = fmaxf(__fdiv_rn(red[0], (float)n), 1e-5f);
    for(int i=threadIdx.x;i<n;i+=256){
        float t = rintf(__fdiv_rn(src[i], scale));
        t = fminf(fmaxf(t,-1.f),1.f);
        dst[i] = (int8_t)(int)t;
    }
}

// ---------------- embedding quant (hi/lo split) + gamma quant ----------------
__global__ void prep_emb(const float* tok_emb, const float* attn_nw,
                         const float* ff_nw, const float* fin_nw){
    int i = blockIdx.x*256 + threadIdx.x;
    if(i < VOCAB*D){
        float r = rintf(__fmul_rn(tok_emb[i],1024.f));
        int q = clampi((int)r,-32768,32767);
        g_ehi[i] = (int8_t)(q >> 8);
        g_elo[i] = (uint8_t)(q & 0xff);
    }
    if(blockIdx.x==0){
        int t=threadIdx.x;
        for(int j=t;j<NL*D;j+=256){
            g_gattn[j] = gammaq(attn_nw[j]);
            g_gff[j]   = gammaq(ff_nw[j]);
        }
        if(t<D) g_gfin[t] = gammaq(fin_nw[t]);
    }
}

// ---------------- token+pos embedding ----------------
__global__ void embed_kernel(const int* tokens, const float* tok_emb, const float* pos_emb){
    int i = blockIdx.x*256 + threadIdx.x;
    if(i >= BT*D) return;
    int bt = i >> 6, d = i & 63;
    int t = bt & (T-1);
    int tok = tokens[bt];
    int tq = clampi((int)rintf(__fmul_rn(tok_emb[tok*D+d],1024.f)),-32768,32767);
    int pq = clampi((int)rintf(__fmul_rn(pos_emb[t*D+d],1024.f)),-32768,32767);
    g_x[i] = (int8_t)wrap8((tq+pq) >> 3);
}

// ---------------- rmsnorm (x -> h), one warp per row ----------------
__global__ void rmsnorm_kernel(int gsel, int layer){
    int row  = (blockIdx.x*blockDim.x + threadIdx.x) >> 5;
    int lane = threadIdx.x & 31;
    if(row >= BT) return;
    const int* gamma = (gsel==0 ? g_gattn : (gsel==1 ? g_gff : g_gfin));
    if(gsel < 2) gamma += layer*D;
    const int8_t* r = g_x + row*D;
    int x0 = r[lane*2], x1 = r[lane*2+1];
    int ss = x0*x0 + x1*x1;
    #pragma unroll
    for(int o=16;o>0;o>>=1) ss += __shfl_xor_sync(0xffffffffu, ss, o);
    int mean_sq = ss >> 6;
    int lut = min(mean_sq >> 6, 255);
    float bc = (float)(lut*64 + 32);
    int inv = clampi((int)rintf(__fdiv_rn(16384.f, __fsqrt_rn(bc))), 0, 16383);
    int g0 = gamma[lane*2], g1 = gamma[lane*2+1];
    int p0 = (x0*inv) >> 8, p1 = (x1*inv) >> 8;
    // mimic JAX f32 product rounding exactly, then *2^-10 (exact) and floor
    int y0 = (int)floorf(__fmul_rn(__fmul_rn((float)p0,(float)g0), 0.0009765625f));
    int y1 = (int)floorf(__fmul_rn(__fmul_rn((float)p1,(float)g1), 0.0009765625f));
    g_h[row*D+lane*2]   = (int8_t)clampi(y0,-128,127);
    g_h[row*D+lane*2+1] = (int8_t)clampi(y1,-128,127);
}

// ---------------- fused QKV bitlinear (one token per block) ----------------
__global__ void qkv_kernel(int layer){
    __shared__ int sh[16];
    int bt = blockIdx.x;
    if(threadIdx.x < 16) sh[threadIdx.x] = ((const int*)(g_h + bt*D))[threadIdx.x];
    __syncthreads();
    int t = threadIdx.x;            // 0..191
    int sel = t >> 6, o = t & 63;
    const int8_t* wb = (sel==0 ? g_wq : (sel==1 ? g_wk : g_wv)) + layer*D*D + o*D;
    const int* w = (const int*)wb;
    int acc = 0;
    #pragma unroll
    for(int i=0;i<16;i++) acc = __dp4a(sh[i], w[i], acc);
    int8_t out = (int8_t)clampi(acc >> 6, -128, 127);
    (sel==0 ? g_q : (sel==1 ? g_k : g_v))[bt*D+o] = out;
}

// ---------------- causal attention (one warp per query, K in smem) ----------------
__global__ __launch_bounds__(256,2) void attn_kernel(){
    __shared__ unsigned sK[T*8];            // K rows as 8 u32 each (32 KB)
    int bh = blockIdx.y; int b = bh >> 1, h = bh & 1;
    int warp = threadIdx.x >> 5, lane = threadIdx.x & 31;

    const int8_t* kbase = g_k + (b*T)*D + h*HD;
    for(int idx=threadIdx.x; idx < T*8; idx += 256){
        int k = idx >> 3, w = idx & 7;
        sK[idx] = ((const unsigned*)(kbase + k*D))[w];
    }
    __syncthreads();

    int q = blockIdx.x*8 + warp;
    const unsigned* qv = (const unsigned*)(g_q + (b*T + q)*D + h*HD);
    unsigned qr[8];
    #pragma unroll
    for(int w=0;w<8;w++) qr[w] = qv[w];

    const int NEG = (int)0x80000000;
    int sc[32];
    int mx = NEG;
    #pragma unroll
    for(int j=0;j<32;j++){
        sc[j] = NEG;
        if(j*32 <= q){                       // warp-uniform causal cull
            int k = j*32 + lane;
            if(k <= q){
                int acc = 0;
                #pragma unroll
                for(int w=0;w<8;w++) acc = __dp4a((int)qr[w], (int)sK[k*8+w], acc);
                float p = __fmul_rn((float)acc, 45.f);
                int s = (int)floorf(__fmul_rn(p, 0.00390625f));
                sc[j] = s; mx = max(mx, s);
            }
        }
    }
    #pragma unroll
    for(int o=16;o>0;o>>=1) mx = max(mx, __shfl_xor_sync(0xffffffffu, mx, o));

    int su = 0;
    #pragma unroll
    for(int j=0;j<32;j++){
        if(sc[j] != NEG){
            int sh = sc[j] - mx;
            int ea = (sh>=-3) ? 256 + sh*64
                   : (sh>=-8) ? 64 + (sh+3)*11
                   : (sh>=-24)? sh + 24 : 0;
            sc[j] = ea; su += ea;
        } else sc[j] = 0;
    }
    #pragma unroll
    for(int o=16;o>0;o>>=1) su += __shfl_xor_sync(0xffffffffu, su, o);
    float sf = (float)max(su, 1);

    int acc[32];
    #pragma unroll
    for(int d=0;d<32;d++) acc[d]=0;
    const int8_t* vbase = g_v + (b*T)*D + h*HD;
    #pragma unroll
    for(int j=0;j<32;j++){
        if(j*32 <= q){
            int k = j*32 + lane;
            if(k <= q && sc[j] > 0){
                int p = clampi((int)rintf(__fmul_rn(__fdiv_rn((float)sc[j], sf), 255.f)), 0, 255);
                const unsigned* vr = (const unsigned*)(vbase + k*D);
                #pragma unroll
                for(int w=0;w<8;w++){
                    unsigned u = vr[w];
                    acc[4*w+0] += p * ((int)(u<<24)>>24);
                    acc[4*w+1] += p * ((int)(u<<16)>>24);
                    acc[4*w+2] += p * ((int)(u<< 8)>>24);
                    acc[4*w+3] += p * ((int) u     >>24);
                }
            }
        }
    }
    #pragma unroll
    for(int d=0;d<32;d++){
        #pragma unroll
        for(int o=16;o>0;o>>=1) acc[d] += __shfl_xor_sync(0xffffffffu, acc[d], o);
    }
    if(lane==0){
        unsigned* out = (unsigned*)(g_a + (b*T + q)*D + h*HD);
        #pragma unroll
        for(int w=0;w<8;w++){
            unsigned r =  ((unsigned)(wrap8(acc[4*w+0]>>8) & 0xff))
                       | (((unsigned)(wrap8(acc[4*w+1]>>8) & 0xff)) << 8)
                       | (((unsigned)(wrap8(acc[4*w+2]>>8) & 0xff)) << 16)
                       | (((unsigned)(wrap8(acc[4*w+3]>>8) & 0xff)) << 24);
            out[w] = r;
        }
    }
}

// ---------------- O projection + residual ----------------
__global__ void oproj_kernel(int layer){
    __shared__ int sa[16];
    int bt = blockIdx.x;
    if(threadIdx.x < 16) sa[threadIdx.x] = ((const int*)(g_a + bt*D))[threadIdx.x];
    __syncthreads();
    int o = threadIdx.x;  // 64
    const int* w = (const int*)(g_wo + layer*D*D + o*D);
    int acc = 0;
    #pragma unroll
    for(int i=0;i<16;i++) acc = __dp4a(sa[i], w[i], acc);
    int r = clampi(acc >> 6, -128, 127);
    int xv = g_x[bt*D+o];
    g_x[bt*D+o] = (int8_t)wrap8(xv + r);
}

// ---------------- FFN up (+relu) ----------------
__global__ void up_kernel(int layer){
    __shared__ int sh[16];
    int bt = blockIdx.x;
    if(threadIdx.x < 16) sh[threadIdx.x] = ((const int*)(g_h + bt*D))[threadIdx.x];
    __syncthreads();
    int o = threadIdx.x;  // 256
    const int* w = (const int*)(g_wup + layer*DFF*D + o*D);
    int acc = 0;
    #pragma unroll
    for(int i=0;i<16;i++) acc = __dp4a(sh[i], w[i], acc);
    int u = clampi(acc >> 6, -128, 127);
    g_u[bt*DFF+o] = (int8_t)max(u, 0);
}

// ---------------- FFN down + residual ----------------
__global__ void down_kernel(int layer){
    __shared__ int su[64];
    int bt = blockIdx.x;
    if(threadIdx.x < 64) su[threadIdx.x] = ((const int*)(g_u + bt*DFF))[threadIdx.x];
    __syncthreads();
    int o = threadIdx.x;  // 64
    const int* w = (const int*)(g_wdn + layer*D*DFF + o*DFF);
    int acc = 0;
    #pragma unroll
    for(int i=0;i<64;i++) acc = __dp4a(su[i], w[i], acc);
    int r = clampi(acc >> 6, -128, 127);
    int xv = g_x[bt*D+o];
    g_x[bt*D+o] = (int8_t)wrap8(xv + r);
}

// ---------------- logits: int8 x Q5.10 split hi/lo dp4a ----------------
__global__ void logits_kernel(float* __restrict__ out){
    __shared__ int shh[16];
    int bt = blockIdx.y;
    if(threadIdx.x < 16) shh[threadIdx.x] = ((const int*)(g_h + bt*D))[threadIdx.x];
    __syncthreads();
    int v0 = blockIdx.x*1024 + threadIdx.x*4;
    float4 res;
    float* rp = (float*)&res;
    #pragma unroll
    for(int i=0;i<4;i++){
        int v = v0 + i;
        const int*      hi = (const int*)     (g_ehi + v*D);
        const unsigned* lo = (const unsigned*)(g_elo + v*D);
        int ah = 0, al = 0;
        #pragma unroll
        for(int w=0;w<16;w++){
            ah = __dp4a(shh[w], hi[w], ah);
            al = dp4a_su(shh[w], lo[w], al);
        }
        int acc = ah*256 + al;
        rp[i] = __fmul_rn((float)acc, 1.220703125e-4f);   // 2^-13 exact
    }
    ((float4*)(out + (size_t)bt*VOCAB))[blockIdx.x*256 + threadIdx.x] = res;
}

// ---------------- launch ----------------
extern "C" void kernel_launch(void* const* d_in, const int* in_sizes, int n_in,
                              void* d_out, int out_size){
    const int*   tokens  = (const int*)  d_in[0];
    const float* tok_emb = (const float*)d_in[1];
    const float* pos_emb = (const float*)d_in[2];
    const float* attn_nw = (const float*)d_in[3];
    const float* qw      = (const float*)d_in[4];
    const float* kw      = (const float*)d_in[5];
    const float* vw      = (const float*)d_in[6];
    const float* ow      = (const float*)d_in[7];
    const float* ff_nw   = (const float*)d_in[8];
    const float* up      = (const float*)d_in[9];
    const float* dn      = (const float*)d_in[10];
    const float* fin_nw  = (const float*)d_in[11];
    float* out = (float*)d_out;

    quant_weights<<<24,256>>>(qw,kw,vw,ow,up,dn);
    prep_emb<<<(VOCAB*D+255)/256,256>>>(tok_emb, attn_nw, ff_nw, fin_nw);
    embed_kernel<<<(BT*D+255)/256,256>>>(tokens, tok_emb, pos_emb);

    for(int l=0;l<NL;l++){
        rmsnorm_kernel<<<BT/8,256>>>(0,l);
        qkv_kernel<<<BT,192>>>(l);
        attn_kernel<<<dim3(T/8, BATCH*H),256>>>();
        oproj_kernel<<<BT,64>>>(l);
        rmsnorm_kernel<<<BT/8,256>>>(1,l);
        up_kernel<<<BT,256>>>(l);
        down_kernel<<<BT,64>>>(l);
    }
    rmsnorm_kernel<<<BT/8,256>>>(2,0);
    logits_kernel<<<dim3(VOCAB/1024, BT),256>>>(out);
}

// round 2
// speedup vs baseline: 5.9363x; 5.9363x over previous
#include <cuda_runtime.h>
#include <cstdint>

#define BATCH 4
#define T 1024
#define D 64
#define H 2
#define HD 32
#define DFF 256
#define NL 4
#define VOCAB 8192
#define BT (BATCH*T)

// ---------------- device scratch (no allocs allowed) ----------------
__device__ __align__(16) int8_t  g_x[BT*D];
__device__ __align__(16) int8_t  g_h[BT*D];
__device__ __align__(16) int8_t  g_q[BT*D];
__device__ __align__(16) int8_t  g_k[BT*D];
__device__ __align__(16) int8_t  g_v[BT*D];
__device__ __align__(16) int8_t  g_a[BT*D];
__device__ __align__(16) uint8_t g_p[BATCH*H*T*T];   // 8MB probs
__device__ __align__(16) int8_t  g_wq[NL*D*D], g_wk[NL*D*D], g_wv[NL*D*D], g_wo[NL*D*D];
__device__ __align__(16) int8_t  g_wup[NL*DFF*D], g_wdn[NL*D*DFF];
__device__ __align__(16) int     g_gattn[NL*D], g_gff[NL*D], g_gfin[D];
__device__ __align__(16) int8_t  g_ehi[VOCAB*D];
__device__ __align__(16) uint8_t g_elo[VOCAB*D];

// ---------------- helpers ----------------
__device__ __forceinline__ int wrap8(int v){ return (int)(signed char)(v & 0xff); }
__device__ __forceinline__ int clampi(int v,int lo,int hi){ return min(max(v,lo),hi); }
__device__ __forceinline__ int dp4a_su(int a, unsigned b, int c){
    int r; asm("dp4a.s32.u32 %0,%1,%2,%3;" : "=r"(r) : "r"(a),"r"(b),"r"(c)); return r;
}
__device__ __forceinline__ int gammaq(float w){
    float c = fminf(fmaxf(w,-2.f),2.f);
    float r = rintf(__fmul_rn(c,1024.f));
    return clampi((int)r,-32768,32767);
}
// exact rmsnorm piece: given x0,x1 (int8 vals of dims 2l,2l+1), full-warp lanes
__device__ __forceinline__ void rms_pair(int x0,int x1,int g0,int g1,int& y0,int& y1){
    int ss = x0*x0 + x1*x1;
    #pragma unroll
    for(int o=16;o>0;o>>=1) ss += __shfl_xor_sync(0xffffffffu, ss, o);
    int mean_sq = ss >> 6;
    int lut = min(mean_sq >> 6, 255);
    float bc = (float)(lut*64 + 32);
    int inv = clampi((int)rintf(__fdiv_rn(16384.f, __fsqrt_rn(bc))), 0, 16383);
    int p0 = (x0*inv) >> 8, p1 = (x1*inv) >> 8;
    y0 = clampi((int)floorf(__fmul_rn(__fmul_rn((float)p0,(float)g0), 0.0009765625f)),-128,127);
    y1 = clampi((int)floorf(__fmul_rn(__fmul_rn((float)p1,(float)g1), 0.0009765625f)),-128,127);
}

// ---------------- weight ternarization ----------------
__global__ void quant_weights(const float* qw, const float* kw, const float* vw,
                              const float* ow, const float* up, const float* dn){
    int m = blockIdx.x; const float* src; int8_t* dst; int n;
    if(m < 16){
        int l = m >> 2, wsel = m & 3; n = D*D;
        const float* bases[4] = {qw,kw,vw,ow};
        int8_t* dsts[4] = {g_wq,g_wk,g_wv,g_wo};
        src = bases[wsel] + l*n; dst = dsts[wsel] + l*n;
    } else if(m < 20){ int l=m-16; n=DFF*D; src=up+l*n; dst=g_wup+l*n; }
    else             { int l=m-20; n=D*DFF; src=dn+l*n; dst=g_wdn+l*n; }

    __shared__ float red[256];
    float s = 0.f;
    for(int i=threadIdx.x;i<n;i+=256) s += fabsf(src[i]);
    red[threadIdx.x]=s; __syncthreads();
    for(int o=128;o>0;o>>=1){ if(threadIdx.x<o) red[threadIdx.x]+=red[threadIdx.x+o]; __syncthreads(); }
    float scale = fmaxf(__fdiv_rn(red[0], (float)n), 1e-5f);
    for(int i=threadIdx.x;i<n;i+=256){
        float t = rintf(__fdiv_rn(src[i], scale));
        t = fminf(fmaxf(t,-1.f),1.f);
        dst[i] = (int8_t)(int)t;
    }
}

// ---------------- embedding quant (hi/lo split) + gamma quant ----------------
__global__ void prep_emb(const float* tok_emb, const float* attn_nw,
                         const float* ff_nw, const float* fin_nw){
    int i = blockIdx.x*256 + threadIdx.x;
    if(i < VOCAB*D){
        float r = rintf(__fmul_rn(tok_emb[i],1024.f));
        int q = clampi((int)r,-32768,32767);
        g_ehi[i] = (int8_t)(q >> 8);
        g_elo[i] = (uint8_t)(q & 0xff);
    }
    if(blockIdx.x==0){
        int t=threadIdx.x;
        for(int j=t;j<NL*D;j+=256){
            g_gattn[j] = gammaq(attn_nw[j]);
            g_gff[j]   = gammaq(ff_nw[j]);
        }
        if(t<D) g_gfin[t] = gammaq(fin_nw[t]);
    }
}

// ---------------- token+pos embedding ----------------
__global__ void embed_kernel(const int* tokens, const float* tok_emb, const float* pos_emb){
    int i = blockIdx.x*256 + threadIdx.x;
    if(i >= BT*D) return;
    int bt = i >> 6, d = i & 63;
    int t = bt & (T-1);
    int tok = tokens[bt];
    int tq = clampi((int)rintf(__fmul_rn(tok_emb[tok*D+d],1024.f)),-32768,32767);
    int pq = clampi((int)rintf(__fmul_rn(pos_emb[t*D+d],1024.f)),-32768,32767);
    g_x[i] = (int8_t)wrap8((tq+pq) >> 3);
}

// ---------------- final rmsnorm (x -> g_h), one warp per row ----------------
__global__ void rmsnorm_final_kernel(){
    int row  = (blockIdx.x*blockDim.x + threadIdx.x) >> 5;
    int lane = threadIdx.x & 31;
    if(row >= BT) return;
    const int8_t* r = g_x + row*D;
    int x0 = r[lane*2], x1 = r[lane*2+1];
    int y0,y1;
    rms_pair(x0,x1,g_gfin[lane*2],g_gfin[lane*2+1],y0,y1);
    g_h[row*D+lane*2]   = (int8_t)y0;
    g_h[row*D+lane*2+1] = (int8_t)y1;
}

// ---------------- fused rmsnorm + QKV: 8 tokens per block ----------------
__global__ __launch_bounds__(256) void qkv_norm_kernel(int layer){
    __shared__ int sh[8*16];
    int tid = threadIdx.x, warp = tid>>5, lane = tid&31;
    int tok = blockIdx.x*8 + warp;
    // phase 1: rmsnorm, one warp per token
    {
        const int8_t* xr = g_x + tok*D;
        int x0 = xr[2*lane], x1 = xr[2*lane+1];
        const int* gm = g_gattn + layer*D;
        int y0,y1;
        rms_pair(x0,x1,gm[2*lane],gm[2*lane+1],y0,y1);
        uint8_t* hb = (uint8_t*)sh + warp*64;
        hb[2*lane]   = (uint8_t)(y0 & 0xff);
        hb[2*lane+1] = (uint8_t)(y1 & 0xff);
    }
    __syncthreads();
    // phase 2: QKV, weight row in registers, reused over 8 tokens
    if(tid < 192){
        int sel = tid>>6, o = tid&63;
        const int8_t* wb = (sel==0 ? g_wq : (sel==1 ? g_wk : g_wv)) + layer*D*D + o*D;
        const int* w = (const int*)wb;
        int wr[16];
        #pragma unroll
        for(int i=0;i<16;i++) wr[i] = w[i];
        int8_t* dst = (sel==0 ? g_q : (sel==1 ? g_k : g_v));
        #pragma unroll
        for(int t=0;t<8;t++){
            int acc = 0;
            #pragma unroll
            for(int i=0;i<16;i++) acc = __dp4a(sh[t*16+i], wr[i], acc);
            dst[(blockIdx.x*8+t)*D + o] = (int8_t)clampi(acc>>6,-128,127);
        }
    }
}

// ---------------- attention pass 1: scores + hw softmax -> packed u8 probs ----------------
__global__ __launch_bounds__(256) void attn_score_kernel(){
    __shared__ unsigned sK[T*9];     // padded rows: conflict-free
    int bh = blockIdx.y; int b = bh>>1, h = bh&1;
    int warp = threadIdx.x>>5, lane = threadIdx.x&31;

    const unsigned* kb = (const unsigned*)g_k + (b*T)*16 + h*8;
    for(int idx=threadIdx.x; idx<T*8; idx+=256){
        int k = idx>>3, w = idx&7;
        sK[k*9+w] = kb[k*16+w];
    }
    __syncthreads();

    int q = blockIdx.x*8 + warp;
    const unsigned* qv = (const unsigned*)g_q + (b*T+q)*16 + h*8;
    unsigned qr[8];
    #pragma unroll
    for(int w=0;w<8;w++) qr[w] = qv[w];

    int jmax = q>>5;
    const int NEG = (int)0x80000000;
    int sc[32];
    int mx = NEG;
    #pragma unroll
    for(int j=0;j<32;j++){
        sc[j] = NEG;
        if(j <= jmax){
            int k = j*32 + lane;
            if(k <= q){
                int acc = 0;
                #pragma unroll
                for(int w=0;w<8;w++) acc = __dp4a((int)qr[w], (int)sK[k*9+w], acc);
                float p = __fmul_rn((float)acc, 45.f);
                int s = (int)floorf(__fmul_rn(p, 0.00390625f));
                sc[j] = s; mx = max(mx, s);
            }
        }
    }
    #pragma unroll
    for(int o=16;o>0;o>>=1) mx = max(mx, __shfl_xor_sync(0xffffffffu, mx, o));

    int su = 0;
    #pragma unroll
    for(int j=0;j<32;j++){
        if(sc[j] != NEG){
            int sh = sc[j] - mx;
            int ea = (sh>=-3) ? 256 + sh*64
                   : (sh>=-8) ? 64 + (sh+3)*11
                   : (sh>=-24)? sh + 24 : 0;
            sc[j] = ea; su += ea;
        } else sc[j] = 0;
    }
    #pragma unroll
    for(int o=16;o>0;o>>=1) su += __shfl_xor_sync(0xffffffffu, su, o);
    float sf = (float)max(su, 1);

    uint8_t* prow = g_p + ((size_t)(bh*T + q) << 10);
    #pragma unroll
    for(int j=0;j<32;j++){
        if(j <= jmax){
            int p = 0;
            if(sc[j] > 0)
                p = clampi((int)rintf(__fmul_rn(__fdiv_rn((float)sc[j], sf), 255.f)), 0, 255);
            prow[j*32+lane] = (uint8_t)p;
        }
    }
}

// ---------------- attention pass 2: AV via dp4a on transposed V ----------------
__global__ __launch_bounds__(256) void attn_av_kernel(){
    __shared__ unsigned sVT[(T/4)*32];   // [chunk][dim] : 4 keys packed per word, 32KB
    int bh = blockIdx.y; int b = bh>>1, h = bh&1;
    int warp = threadIdx.x>>5, lane = threadIdx.x&31;

    const unsigned* vb = (const unsigned*)g_v + (b*T)*16 + h*8;
    uint8_t* svb = (uint8_t*)sVT;
    for(int idx=threadIdx.x; idx<T*8; idx+=256){
        int k = idx>>3, w = idx&7;
        unsigned u = vb[k*16+w];
        int c = k>>2, r = k&3, d0 = w*4;
        svb[c*128 + (d0+0)*4 + r] = (uint8_t)( u        & 0xff);
        svb[c*128 + (d0+1)*4 + r] = (uint8_t)((u >> 8)  & 0xff);
        svb[c*128 + (d0+2)*4 + r] = (uint8_t)((u >> 16) & 0xff);
        svb[c*128 + (d0+3)*4 + r] = (uint8_t)((u >> 24) & 0xff);
    }
    __syncthreads();

    int q = blockIdx.x*8 + warp;
    int d = lane;
    const unsigned* prow = (const unsigned*)(g_p + ((size_t)(bh*T + q) << 10));
    int cmax = q>>2;
    int acc = 0;
    int c = 0;
    for(; c+4 <= cmax+1; c+=4){
        unsigned p0=prow[c], p1=prow[c+1], p2=prow[c+2], p3=prow[c+3];
        acc = dp4a_su((int)sVT[(c+0)*32+d], p0, acc);
        acc = dp4a_su((int)sVT[(c+1)*32+d], p1, acc);
        acc = dp4a_su((int)sVT[(c+2)*32+d], p2, acc);
        acc = dp4a_su((int)sVT[(c+3)*32+d], p3, acc);
    }
    for(; c<=cmax; c++)
        acc = dp4a_su((int)sVT[c*32+d], prow[c], acc);

    g_a[(b*T+q)*D + h*HD + d] = (int8_t)wrap8(acc>>8);
}

// ---------------- fused oproj + residual + rmsnorm + FFN + residual ----------------
__global__ __launch_bounds__(256) void ffn_fused_kernel(int layer){
    __shared__ int sa[16];
    __shared__ int sx[64];
    __shared__ int sh[16];
    __shared__ uint8_t su8[256];
    int bt = blockIdx.x, tid = threadIdx.x;

    if(tid < 16) sa[tid] = ((const int*)g_a)[bt*16 + tid];
    __syncthreads();

    if(tid < 64){
        const int* w = (const int*)(g_wo + layer*D*D) + tid*16;
        int acc = 0;
        #pragma unroll
        for(int i=0;i<16;i++) acc = __dp4a(sa[i], w[i], acc);
        int r = clampi(acc>>6,-128,127);
        sx[tid] = wrap8((int)g_x[bt*D+tid] + r);
    }
    __syncthreads();

    if(tid < 32){
        int l = tid;
        int x0 = sx[2*l], x1 = sx[2*l+1];
        const int* gm = g_gff + layer*D;
        int y0,y1;
        rms_pair(x0,x1,gm[2*l],gm[2*l+1],y0,y1);
        uint8_t* hb = (uint8_t*)sh;
        hb[2*l]   = (uint8_t)(y0 & 0xff);
        hb[2*l+1] = (uint8_t)(y1 & 0xff);
    }
    __syncthreads();

    {   // up + relu: all 256 threads
        const int* w = (const int*)(g_wup + layer*DFF*D) + tid*16;
        int acc = 0;
        #pragma unroll
        for(int i=0;i<16;i++) acc = __dp4a(sh[i], w[i], acc);
        int u = clampi(acc>>6,-128,127);
        su8[tid] = (uint8_t)max(u,0);
    }
    __syncthreads();

    if(tid < 64){
        const int* w = (const int*)(g_wdn + layer*D*DFF) + tid*64;
        const int* suw = (const int*)su8;
        int acc = 0;
        #pragma unroll
        for(int i=0;i<64;i++) acc = __dp4a(suw[i], w[i], acc);
        int r = clampi(acc>>6,-128,127);
        g_x[bt*D+tid] = (int8_t)wrap8(sx[tid] + r);
    }
}

// ---------------- logits: tiled 16 tokens x 512 vocab, emb rows in registers ----------------
__global__ __launch_bounds__(256) void logits_kernel(float* __restrict__ out){
    __shared__ int shh[256];          // 16 tokens x 16 words of h
    int btb = blockIdx.y;             // token tile (16 tokens)
    int vb  = blockIdx.x * 512;       // vocab tile
    int tid = threadIdx.x;
    shh[tid] = ((const int*)g_h)[btb*256 + tid];
    __syncthreads();

    #pragma unroll
    for(int half=0; half<2; half++){
        int v = vb + half*256 + tid;
        const int*      hi = (const int*)     g_ehi + v*16;
        const unsigned* lo = (const unsigned*)g_elo + v*16;
        int hr[16]; unsigned lr[16];
        #pragma unroll
        for(int w=0;w<16;w++){ hr[w]=hi[w]; lr[w]=lo[w]; }
        #pragma unroll
        for(int t=0;t<16;t++){
            int ah=0, al=0;
            #pragma unroll
            for(int w=0;w<16;w++){
                int s = shh[t*16+w];
                ah = __dp4a(s, hr[w], ah);
                al = dp4a_su(s, lr[w], al);
            }
            int acc = ah*256 + al;
            out[(size_t)(btb*16+t)*VOCAB + v] = __fmul_rn((float)acc, 1.220703125e-4f);
        }
    }
}

// ---------------- launch ----------------
extern "C" void kernel_launch(void* const* d_in, const int* in_sizes, int n_in,
                              void* d_out, int out_size){
    const int*   tokens  = (const int*)  d_in[0];
    const float* tok_emb = (const float*)d_in[1];
    const float* pos_emb = (const float*)d_in[2];
    const float* attn_nw = (const float*)d_in[3];
    const float* qw      = (const float*)d_in[4];
    const float* kw      = (const float*)d_in[5];
    const float* vw      = (const float*)d_in[6];
    const float* ow      = (const float*)d_in[7];
    const float* ff_nw   = (const float*)d_in[8];
    const float* up      = (const float*)d_in[9];
    const float* dn      = (const float*)d_in[10];
    const float* fin_nw  = (const float*)d_in[11];
    float* out = (float*)d_out;

    quant_weights<<<24,256>>>(qw,kw,vw,ow,up,dn);
    prep_emb<<<(VOCAB*D+255)/256,256>>>(tok_emb, attn_nw, ff_nw, fin_nw);
    embed_kernel<<<(BT*D+255)/256,256>>>(tokens, tok_emb, pos_emb);

    for(int l=0;l<NL;l++){
        qkv_norm_kernel<<<BT/8,256>>>(l);
        attn_score_kernel<<<dim3(T/8, BATCH*H),256>>>();
        attn_av_kernel<<<dim3(T/8, BATCH*H),256>>>();
        ffn_fused_kernel<<<BT,256>>>(l);
    }
    rmsnorm_final_kernel<<<BT/8,256>>>();
    logits_kernel<<<dim3(VOCAB/512, BT/16),256>>>(out);
}

// round 3
// speedup vs baseline: 6.5997x; 1.1117x over previous
#include <cuda_runtime.h>
#include <cstdint>

#define BATCH 4
#define T 1024
#define D 64
#define H 2
#define HD 32
#define DFF 256
#define NL 4
#define VOCAB 8192
#define BT (BATCH*T)

// ---------------- device scratch (no allocs allowed) ----------------
__device__ __align__(16) int8_t  g_x[BT*D];
__device__ __align__(16) int8_t  g_h[BT*D];
__device__ __align__(16) int8_t  g_q[BT*D];
__device__ __align__(16) int8_t  g_k[BT*D];
__device__ __align__(16) int8_t  g_v[BT*D];
__device__ __align__(16) int8_t  g_a[BT*D];
__device__ __align__(16) int8_t  g_wq[NL*D*D], g_wk[NL*D*D], g_wv[NL*D*D], g_wo[NL*D*D];
__device__ __align__(16) int8_t  g_wup[NL*DFF*D], g_wdn[NL*D*DFF];
__device__ __align__(16) int     g_gattn[NL*D], g_gff[NL*D], g_gfin[D];
__device__ __align__(16) int8_t  g_ehi[VOCAB*D];
__device__ __align__(16) uint8_t g_elo[VOCAB*D];

// ---------------- helpers ----------------
__device__ __forceinline__ int wrap8(int v){ return (int)(signed char)(v & 0xff); }
__device__ __forceinline__ int clampi(int v,int lo,int hi){ return min(max(v,lo),hi); }
__device__ __forceinline__ int dp4a_su(int a, unsigned b, int c){
    int r; asm("dp4a.s32.u32 %0,%1,%2,%3;" : "=r"(r) : "r"(a),"r"(b),"r"(c)); return r;
}
__device__ __forceinline__ int gammaq(float w){
    float c = fminf(fmaxf(w,-2.f),2.f);
    float r = rintf(__fmul_rn(c,1024.f));
    return clampi((int)r,-32768,32767);
}
__device__ __forceinline__ void rms_pair(int x0,int x1,int g0,int g1,int& y0,int& y1){
    int ss = x0*x0 + x1*x1;
    #pragma unroll
    for(int o=16;o>0;o>>=1) ss += __shfl_xor_sync(0xffffffffu, ss, o);
    int mean_sq = ss >> 6;
    int lut = min(mean_sq >> 6, 255);
    float bc = (float)(lut*64 + 32);
    int inv = clampi((int)rintf(__fdiv_rn(16384.f, __fsqrt_rn(bc))), 0, 16383);
    int p0 = (x0*inv) >> 8, p1 = (x1*inv) >> 8;
    y0 = clampi((int)floorf(__fmul_rn(__fmul_rn((float)p0,(float)g0), 0.0009765625f)),-128,127);
    y1 = clampi((int)floorf(__fmul_rn(__fmul_rn((float)p1,(float)g1), 0.0009765625f)),-128,127);
}
// m16n8k32 int8 MMA (Ampere-style, valid on sm_80+ incl. Blackwell)
__device__ __forceinline__ void mma_s8s8(int* d, const int* a, const int* b){
    asm("mma.sync.aligned.m16n8k32.row.col.s32.s8.s8.s32 "
        "{%0,%1,%2,%3},{%4,%5,%6,%7},{%8,%9},{%0,%1,%2,%3};"
        : "+r"(d[0]),"+r"(d[1]),"+r"(d[2]),"+r"(d[3])
        : "r"(a[0]),"r"(a[1]),"r"(a[2]),"r"(a[3]),"r"(b[0]),"r"(b[1]));
}
__device__ __forceinline__ void mma_s8u8(int* d, const int* a, const int* b){
    asm("mma.sync.aligned.m16n8k32.row.col.s32.s8.u8.s32 "
        "{%0,%1,%2,%3},{%4,%5,%6,%7},{%8,%9},{%0,%1,%2,%3};"
        : "+r"(d[0]),"+r"(d[1]),"+r"(d[2]),"+r"(d[3])
        : "r"(a[0]),"r"(a[1]),"r"(a[2]),"r"(a[3]),"r"(b[0]),"r"(b[1]));
}

// ---------------- weight ternarization ----------------
__global__ void quant_weights(const float* qw, const float* kw, const float* vw,
                              const float* ow, const float* up, const float* dn){
    int m = blockIdx.x; const float* src; int8_t* dst; int n;
    if(m < 16){
        int l = m >> 2, wsel = m & 3; n = D*D;
        const float* bases[4] = {qw,kw,vw,ow};
        int8_t* dsts[4] = {g_wq,g_wk,g_wv,g_wo};
        src = bases[wsel] + l*n; dst = dsts[wsel] + l*n;
    } else if(m < 20){ int l=m-16; n=DFF*D; src=up+l*n; dst=g_wup+l*n; }
    else             { int l=m-20; n=D*DFF; src=dn+l*n; dst=g_wdn+l*n; }

    __shared__ float red[256];
    float s = 0.f;
    for(int i=threadIdx.x;i<n;i+=256) s += fabsf(src[i]);
    red[threadIdx.x]=s; __syncthreads();
    for(int o=128;o>0;o>>=1){ if(threadIdx.x<o) red[threadIdx.x]+=red[threadIdx.x+o]; __syncthreads(); }
    float scale = fmaxf(__fdiv_rn(red[0], (float)n), 1e-5f);
    for(int i=threadIdx.x;i<n;i+=256){
        float t = rintf(__fdiv_rn(src[i], scale));
        t = fminf(fmaxf(t,-1.f),1.f);
        dst[i] = (int8_t)(int)t;
    }
}

// ---------------- embedding quant (hi/lo split) + gamma quant ----------------
__global__ void prep_emb(const float* tok_emb, const float* attn_nw,
                         const float* ff_nw, const float* fin_nw){
    int i = blockIdx.x*256 + threadIdx.x;
    if(i < VOCAB*D){
        float r = rintf(__fmul_rn(tok_emb[i],1024.f));
        int q = clampi((int)r,-32768,32767);
        g_ehi[i] = (int8_t)(q >> 8);
        g_elo[i] = (uint8_t)(q & 0xff);
    }
    if(blockIdx.x==0){
        int t=threadIdx.x;
        for(int j=t;j<NL*D;j+=256){
            g_gattn[j] = gammaq(attn_nw[j]);
            g_gff[j]   = gammaq(ff_nw[j]);
        }
        if(t<D) g_gfin[t] = gammaq(fin_nw[t]);
    }
}

// ---------------- token+pos embedding ----------------
__global__ void embed_kernel(const int* tokens, const float* tok_emb, const float* pos_emb){
    int i = blockIdx.x*256 + threadIdx.x;
    if(i >= BT*D) return;
    int bt = i >> 6, d = i & 63;
    int t = bt & (T-1);
    int tok = tokens[bt];
    int tq = clampi((int)rintf(__fmul_rn(tok_emb[tok*D+d],1024.f)),-32768,32767);
    int pq = clampi((int)rintf(__fmul_rn(pos_emb[t*D+d],1024.f)),-32768,32767);
    g_x[i] = (int8_t)wrap8((tq+pq) >> 3);
}

// ---------------- final rmsnorm (x -> g_h), one warp per row ----------------
__global__ void rmsnorm_final_kernel(){
    int row  = (blockIdx.x*blockDim.x + threadIdx.x) >> 5;
    int lane = threadIdx.x & 31;
    if(row >= BT) return;
    const int8_t* r = g_x + row*D;
    int x0 = r[lane*2], x1 = r[lane*2+1];
    int y0,y1;
    rms_pair(x0,x1,g_gfin[lane*2],g_gfin[lane*2+1],y0,y1);
    g_h[row*D+lane*2]   = (int8_t)y0;
    g_h[row*D+lane*2+1] = (int8_t)y1;
}

// ---------------- fused rmsnorm + QKV: 8 tokens per block ----------------
__global__ __launch_bounds__(256) void qkv_norm_kernel(int layer){
    __shared__ int sh[8*16];
    int tid = threadIdx.x, warp = tid>>5, lane = tid&31;
    int tok = blockIdx.x*8 + warp;
    {
        const int8_t* xr = g_x + tok*D;
        int x0 = xr[2*lane], x1 = xr[2*lane+1];
        const int* gm = g_gattn + layer*D;
        int y0,y1;
        rms_pair(x0,x1,gm[2*lane],gm[2*lane+1],y0,y1);
        uint8_t* hb = (uint8_t*)sh + warp*64;
        hb[2*lane]   = (uint8_t)(y0 & 0xff);
        hb[2*lane+1] = (uint8_t)(y1 & 0xff);
    }
    __syncthreads();
    if(tid < 192){
        int sel = tid>>6, o = tid&63;
        const int8_t* wb = (sel==0 ? g_wq : (sel==1 ? g_wk : g_wv)) + layer*D*D + o*D;
        const int* w = (const int*)wb;
        int wr[16];
        #pragma unroll
        for(int i=0;i<16;i++) wr[i] = w[i];
        int8_t* dst = (sel==0 ? g_q : (sel==1 ? g_k : g_v));
        #pragma unroll
        for(int t=0;t<8;t++){
            int acc = 0;
            #pragma unroll
            for(int i=0;i<16;i++) acc = __dp4a(sh[t*16+i], wr[i], acc);
            dst[(blockIdx.x*8+t)*D + o] = (int8_t)clampi(acc>>6,-128,127);
        }
    }
}

// ---------------- fused attention: scores + softmax + AV ----------------
// dyn smem: sK (T*9 words) | sVT (T/4*32 words) | sP (8 warps * 1024 B)
#define ATTN_SMEM ((T*9 + (T/4)*32)*4 + 8*T)
__global__ __launch_bounds__(256) void attn_fused_kernel(){
    extern __shared__ unsigned dyn[];
    unsigned* sK  = dyn;                    // 9216 words
    unsigned* sVT = dyn + T*9;              // 8192 words
    uint8_t*  sP  = (uint8_t*)(dyn + T*9 + (T/4)*32);
    int bh = blockIdx.y; int b = bh>>1, h = bh&1;
    int warp = threadIdx.x>>5, lane = threadIdx.x&31;

    const unsigned* kb = (const unsigned*)g_k + (b*T)*16 + h*8;
    const unsigned* vb = (const unsigned*)g_v + (b*T)*16 + h*8;
    uint8_t* svb = (uint8_t*)sVT;
    for(int idx=threadIdx.x; idx<T*8; idx+=256){
        int k = idx>>3, w = idx&7;
        sK[k*9+w] = kb[k*16+w];
        unsigned u = vb[k*16+w];
        int c = k>>2, r = k&3, d0 = w*4;
        svb[c*128 + (d0+0)*4 + r] = (uint8_t)( u        & 0xff);
        svb[c*128 + (d0+1)*4 + r] = (uint8_t)((u >> 8)  & 0xff);
        svb[c*128 + (d0+2)*4 + r] = (uint8_t)((u >> 16) & 0xff);
        svb[c*128 + (d0+3)*4 + r] = (uint8_t)((u >> 24) & 0xff);
    }
    __syncthreads();

    int q = blockIdx.x*8 + warp;
    const unsigned* qv = (const unsigned*)g_q + (b*T+q)*16 + h*8;
    unsigned qr[8];
    #pragma unroll
    for(int w=0;w<8;w++) qr[w] = qv[w];

    int jmax = q>>5;
    const int NEG = (int)0x80000000;
    int sc[32];
    int mx = NEG;
    #pragma unroll
    for(int j=0;j<32;j++){
        sc[j] = NEG;
        if(j <= jmax){
            int k = j*32 + lane;
            if(k <= q){
                int acc = 0;
                #pragma unroll
                for(int w=0;w<8;w++) acc = __dp4a((int)qr[w], (int)sK[k*9+w], acc);
                float p = __fmul_rn((float)acc, 45.f);
                int s = (int)floorf(__fmul_rn(p, 0.00390625f));
                sc[j] = s; mx = max(mx, s);
            }
        }
    }
    #pragma unroll
    for(int o=16;o>0;o>>=1) mx = max(mx, __shfl_xor_sync(0xffffffffu, mx, o));

    int su = 0;
    #pragma unroll
    for(int j=0;j<32;j++){
        if(sc[j] != NEG){
            int sh = sc[j] - mx;
            int ea = (sh>=-3) ? 256 + sh*64
                   : (sh>=-8) ? 64 + (sh+3)*11
                   : (sh>=-24)? sh + 24 : 0;
            sc[j] = ea; su += ea;
        } else sc[j] = 0;
    }
    #pragma unroll
    for(int o=16;o>0;o>>=1) su += __shfl_xor_sync(0xffffffffu, su, o);
    float sf = (float)max(su, 1);

    uint8_t* prow = sP + warp*T;
    #pragma unroll
    for(int j=0;j<32;j++){
        if(j <= jmax){
            int p = 0;
            if(sc[j] > 0)
                p = clampi((int)rintf(__fmul_rn(__fdiv_rn((float)sc[j], sf), 255.f)), 0, 255);
            prow[j*32+lane] = (uint8_t)p;
        }
    }
    __syncwarp();

    // AV: lane = head dim, dp4a over packed prob/V chunks
    const unsigned* pw = (const unsigned*)prow;
    int d = lane;
    int cmax = q>>2;
    int acc = 0;
    int c = 0;
    for(; c+4 <= cmax+1; c+=4){
        unsigned p0=pw[c], p1=pw[c+1], p2=pw[c+2], p3=pw[c+3];
        acc = dp4a_su((int)sVT[(c+0)*32+d], p0, acc);
        acc = dp4a_su((int)sVT[(c+1)*32+d], p1, acc);
        acc = dp4a_su((int)sVT[(c+2)*32+d], p2, acc);
        acc = dp4a_su((int)sVT[(c+3)*32+d], p3, acc);
    }
    for(; c<=cmax; c++)
        acc = dp4a_su((int)sVT[c*32+d], pw[c], acc);

    g_a[(b*T+q)*D + h*HD + d] = (int8_t)wrap8(acc>>8);
}

// ---------------- fused oproj + residual + rmsnorm + FFN + residual ----------------
__global__ __launch_bounds__(256) void ffn_fused_kernel(int layer){
    __shared__ int sa[16];
    __shared__ int sx[64];
    __shared__ int sh[16];
    __shared__ uint8_t su8[256];
    __shared__ int sred[256];
    int bt = blockIdx.x, tid = threadIdx.x;

    if(tid < 16) sa[tid] = ((const int*)g_a)[bt*16 + tid];
    __syncthreads();

    {   // oproj partials: all 256 threads (o = tid&63, seg = tid>>6)
        int o = tid&63, seg = tid>>6;
        const int* w = (const int*)(g_wo + layer*D*D) + o*16 + seg*4;
        int acc = 0;
        #pragma unroll
        for(int i=0;i<4;i++) acc = __dp4a(sa[seg*4+i], w[i], acc);
        sred[tid] = acc;
    }
    __syncthreads();
    if(tid < 64){
        int acc = sred[tid]+sred[tid+64]+sred[tid+128]+sred[tid+192];
        int r = clampi(acc>>6,-128,127);
        sx[tid] = wrap8((int)g_x[bt*D+tid] + r);
    }
    __syncthreads();

    if(tid < 32){
        int l = tid;
        int x0 = sx[2*l], x1 = sx[2*l+1];
        const int* gm = g_gff + layer*D;
        int y0,y1;
        rms_pair(x0,x1,gm[2*l],gm[2*l+1],y0,y1);
        uint8_t* hb = (uint8_t*)sh;
        hb[2*l]   = (uint8_t)(y0 & 0xff);
        hb[2*l+1] = (uint8_t)(y1 & 0xff);
    }
    __syncthreads();

    {   // up + relu: all 256 threads
        const int* w = (const int*)(g_wup + layer*DFF*D) + tid*16;
        int acc = 0;
        #pragma unroll
        for(int i=0;i<16;i++) acc = __dp4a(sh[i], w[i], acc);
        int u = clampi(acc>>6,-128,127);
        su8[tid] = (uint8_t)max(u,0);
    }
    __syncthreads();

    {   // down partials: all 256 threads (o = tid&63, seg = tid>>6, 16 words each)
        int o = tid&63, seg = tid>>6;
        const int* w = (const int*)(g_wdn + layer*D*DFF) + o*64 + seg*16;
        const int* suw = (const int*)su8 + seg*16;
        int acc = 0;
        #pragma unroll
        for(int i=0;i<16;i++) acc = __dp4a(suw[i], w[i], acc);
        sred[tid] = acc;
    }
    __syncthreads();
    if(tid < 64){
        int acc = sred[tid]+sred[tid+64]+sred[tid+128]+sred[tid+192];
        int r = clampi(acc>>6,-128,127);
        g_x[bt*D+tid] = (int8_t)wrap8(sx[tid] + r);
    }
}

// ---------------- logits via IMMA: warp = 64 tokens x 32 vocab ----------------
__global__ __launch_bounds__(256) void logits_mma_kernel(float* __restrict__ out){
    int warp = threadIdx.x>>5, lane = threadIdx.x&31;
    int g = lane>>2, tg = lane&3;
    int vbase = blockIdx.x*256 + warp*32;
    int mbase = blockIdx.y*64;

    // B fragments (emb hi/lo), reused over 4 M-subtiles
    int bhi[4][2][2], blo[4][2][2];
    #pragma unroll
    for(int nt=0;nt<4;nt++){
        int col = vbase + nt*8 + g;
        const int8_t*  eh = g_ehi + col*64;
        const uint8_t* el = g_elo + col*64;
        #pragma unroll
        for(int kc=0;kc<2;kc++){
            bhi[nt][kc][0] = *(const int*)(eh + kc*32 + tg*4);
            bhi[nt][kc][1] = *(const int*)(eh + kc*32 + 16 + tg*4);
            blo[nt][kc][0] = *(const int*)(el + kc*32 + tg*4);
            blo[nt][kc][1] = *(const int*)(el + kc*32 + 16 + tg*4);
        }
    }
    #pragma unroll
    for(int mt=0;mt<4;mt++){
        int row0 = mbase + mt*16 + g;
        const int8_t* h0 = g_h + row0*64;
        const int8_t* h8 = g_h + (row0+8)*64;
        int a[2][4];
        #pragma unroll
        for(int kc=0;kc<2;kc++){
            a[kc][0] = *(const int*)(h0 + kc*32 + tg*4);
            a[kc][1] = *(const int*)(h8 + kc*32 + tg*4);
            a[kc][2] = *(const int*)(h0 + kc*32 + 16 + tg*4);
            a[kc][3] = *(const int*)(h8 + kc*32 + 16 + tg*4);
        }
        #pragma unroll
        for(int nt=0;nt<4;nt++){
            int dh[4]={0,0,0,0}, dl[4]={0,0,0,0};
            #pragma unroll
            for(int kc=0;kc<2;kc++){
                mma_s8s8(dh, a[kc], bhi[nt][kc]);
                mma_s8u8(dl, a[kc], blo[nt][kc]);
            }
            int col = vbase + nt*8 + 2*tg;
            float2 v0, v1;
            v0.x = __fmul_rn((float)(dh[0]*256+dl[0]), 1.220703125e-4f);
            v0.y = __fmul_rn((float)(dh[1]*256+dl[1]), 1.220703125e-4f);
            v1.x = __fmul_rn((float)(dh[2]*256+dl[2]), 1.220703125e-4f);
            v1.y = __fmul_rn((float)(dh[3]*256+dl[3]), 1.220703125e-4f);
            *(float2*)(out + (size_t)row0*VOCAB + col)     = v0;
            *(float2*)(out + (size_t)(row0+8)*VOCAB + col) = v1;
        }
    }
}

// ---------------- launch ----------------
extern "C" void kernel_launch(void* const* d_in, const int* in_sizes, int n_in,
                              void* d_out, int out_size){
    const int*   tokens  = (const int*)  d_in[0];
    const float* tok_emb = (const float*)d_in[1];
    const float* pos_emb = (const float*)d_in[2];
    const float* attn_nw = (const float*)d_in[3];
    const float* qw      = (const float*)d_in[4];
    const float* kw      = (const float*)d_in[5];
    const float* vw      = (const float*)d_in[6];
    const float* ow      = (const float*)d_in[7];
    const float* ff_nw   = (const float*)d_in[8];
    const float* up      = (const float*)d_in[9];
    const float* dn      = (const float*)d_in[10];
    const float* fin_nw  = (const float*)d_in[11];
    float* out = (float*)d_out;

    cudaFuncSetAttribute(attn_fused_kernel,
                         cudaFuncAttributeMaxDynamicSharedMemorySize, ATTN_SMEM);

    quant_weights<<<24,256>>>(qw,kw,vw,ow,up,dn);
    prep_emb<<<(VOCAB*D+255)/256,256>>>(tok_emb, attn_nw, ff_nw, fin_nw);
    embed_kernel<<<(BT*D+255)/256,256>>>(tokens, tok_emb, pos_emb);

    for(int l=0;l<NL;l++){
        qkv_norm_kernel<<<BT/8,256>>>(l);
        attn_fused_kernel<<<dim3(T/8, BATCH*H),256,ATTN_SMEM>>>();
        ffn_fused_kernel<<<BT,256>>>(l);
    }
    rmsnorm_final_kernel<<<BT/8,256>>>();
    logits_mma_kernel<<<dim3(VOCAB/256, BT/64),256>>>(out);
}

// round 4
// speedup vs baseline: 6.6107x; 1.0017x over previous
#include <cuda_runtime.h>
#include <cstdint>

#define BATCH 4
#define T 1024
#define D 64
#define H 2
#define HD 32
#define DFF 256
#define NL 4
#define VOCAB 8192
#define BT (BATCH*T)

// ---------------- device scratch (no allocs allowed) ----------------
__device__ __align__(16) int8_t  g_x[BT*D];
__device__ __align__(16) int8_t  g_h[BT*D];
__device__ __align__(16) int8_t  g_q[BT*D];
__device__ __align__(16) int8_t  g_k[BT*D];
__device__ __align__(16) int8_t  g_v[BT*D];
__device__ __align__(16) int8_t  g_a[BT*D];
__device__ __align__(16) int8_t  g_wq[NL*D*D], g_wk[NL*D*D], g_wv[NL*D*D], g_wo[NL*D*D];
__device__ __align__(16) int8_t  g_wup[NL*DFF*D], g_wdn[NL*D*DFF];
__device__ __align__(16) int     g_gattn[NL*D], g_gff[NL*D], g_gfin[D];
__device__ __align__(16) int8_t  g_ehi[VOCAB*D];
__device__ __align__(16) uint8_t g_elo[VOCAB*D];

// ---------------- helpers ----------------
__device__ __forceinline__ int wrap8(int v){ return (int)(signed char)(v & 0xff); }
__device__ __forceinline__ int clampi(int v,int lo,int hi){ return min(max(v,lo),hi); }
__device__ __forceinline__ int dp4a_su(int a, unsigned b, int c){
    int r; asm("dp4a.s32.u32 %0,%1,%2,%3;" : "=r"(r) : "r"(a),"r"(b),"r"(c)); return r;
}
__device__ __forceinline__ int gammaq(float w){
    float c = fminf(fmaxf(w,-2.f),2.f);
    float r = rintf(__fmul_rn(c,1024.f));
    return clampi((int)r,-32768,32767);
}
__device__ __forceinline__ void rms_pair(int x0,int x1,int g0,int g1,int& y0,int& y1){
    int ss = x0*x0 + x1*x1;
    #pragma unroll
    for(int o=16;o>0;o>>=1) ss += __shfl_xor_sync(0xffffffffu, ss, o);
    int mean_sq = ss >> 6;
    int lut = min(mean_sq >> 6, 255);
    float bc = (float)(lut*64 + 32);
    int inv = clampi((int)rintf(__fdiv_rn(16384.f, __fsqrt_rn(bc))), 0, 16383);
    int p0 = (x0*inv) >> 8, p1 = (x1*inv) >> 8;
    y0 = clampi((int)floorf(__fmul_rn(__fmul_rn((float)p0,(float)g0), 0.0009765625f)),-128,127);
    y1 = clampi((int)floorf(__fmul_rn(__fmul_rn((float)p1,(float)g1), 0.0009765625f)),-128,127);
}
// m16n8k32 int8 MMA (Ampere-style, valid on sm_80+ incl. Blackwell)
__device__ __forceinline__ void mma_s8s8(int* d, const int* a, const int* b){
    asm("mma.sync.aligned.m16n8k32.row.col.s32.s8.s8.s32 "
        "{%0,%1,%2,%3},{%4,%5,%6,%7},{%8,%9},{%0,%1,%2,%3};"
        : "+r"(d[0]),"+r"(d[1]),"+r"(d[2]),"+r"(d[3])
        : "r"(a[0]),"r"(a[1]),"r"(a[2]),"r"(a[3]),"r"(b[0]),"r"(b[1]));
}
__device__ __forceinline__ void mma_s8u8(int* d, const int* a, const int* b){
    asm("mma.sync.aligned.m16n8k32.row.col.s32.s8.u8.s32 "
        "{%0,%1,%2,%3},{%4,%5,%6,%7},{%8,%9},{%0,%1,%2,%3};"
        : "+r"(d[0]),"+r"(d[1]),"+r"(d[2]),"+r"(d[3])
        : "r"(a[0]),"r"(a[1]),"r"(a[2]),"r"(a[3]),"r"(b[0]),"r"(b[1]));
}

// ---------------- weight ternarization ----------------
__global__ void quant_weights(const float* qw, const float* kw, const float* vw,
                              const float* ow, const float* up, const float* dn){
    int m = blockIdx.x; const float* src; int8_t* dst; int n;
    if(m < 16){
        int l = m >> 2, wsel = m & 3; n = D*D;
        const float* bases[4] = {qw,kw,vw,ow};
        int8_t* dsts[4] = {g_wq,g_wk,g_wv,g_wo};
        src = bases[wsel] + l*n; dst = dsts[wsel] + l*n;
    } else if(m < 20){ int l=m-16; n=DFF*D; src=up+l*n; dst=g_wup+l*n; }
    else             { int l=m-20; n=D*DFF; src=dn+l*n; dst=g_wdn+l*n; }

    __shared__ float red[256];
    float s = 0.f;
    for(int i=threadIdx.x;i<n;i+=256) s += fabsf(src[i]);
    red[threadIdx.x]=s; __syncthreads();
    for(int o=128;o>0;o>>=1){ if(threadIdx.x<o) red[threadIdx.x]+=red[threadIdx.x+o]; __syncthreads(); }
    float scale = fmaxf(__fdiv_rn(red[0], (float)n), 1e-5f);
    for(int i=threadIdx.x;i<n;i+=256){
        float t = rintf(__fdiv_rn(src[i], scale));
        t = fminf(fmaxf(t,-1.f),1.f);
        dst[i] = (int8_t)(int)t;
    }
}

// ---------------- embedding quant (hi/lo split) + gamma quant ----------------
__global__ void prep_emb(const float* tok_emb, const float* attn_nw,
                         const float* ff_nw, const float* fin_nw){
    int i = blockIdx.x*256 + threadIdx.x;
    if(i < VOCAB*D){
        float r = rintf(__fmul_rn(tok_emb[i],1024.f));
        int q = clampi((int)r,-32768,32767);
        g_ehi[i] = (int8_t)(q >> 8);
        g_elo[i] = (uint8_t)(q & 0xff);
    }
    if(blockIdx.x==0){
        int t=threadIdx.x;
        for(int j=t;j<NL*D;j+=256){
            g_gattn[j] = gammaq(attn_nw[j]);
            g_gff[j]   = gammaq(ff_nw[j]);
        }
        if(t<D) g_gfin[t] = gammaq(fin_nw[t]);
    }
}

// ---------------- token+pos embedding ----------------
__global__ void embed_kernel(const int* tokens, const float* tok_emb, const float* pos_emb){
    int i = blockIdx.x*256 + threadIdx.x;
    if(i >= BT*D) return;
    int bt = i >> 6, d = i & 63;
    int t = bt & (T-1);
    int tok = tokens[bt];
    int tq = clampi((int)rintf(__fmul_rn(tok_emb[tok*D+d],1024.f)),-32768,32767);
    int pq = clampi((int)rintf(__fmul_rn(pos_emb[t*D+d],1024.f)),-32768,32767);
    g_x[i] = (int8_t)wrap8((tq+pq) >> 3);
}

// ---------------- final rmsnorm (x -> g_h), one warp per row ----------------
__global__ void rmsnorm_final_kernel(){
    int row  = (blockIdx.x*blockDim.x + threadIdx.x) >> 5;
    int lane = threadIdx.x & 31;
    if(row >= BT) return;
    const int8_t* r = g_x + row*D;
    int x0 = r[lane*2], x1 = r[lane*2+1];
    int y0,y1;
    rms_pair(x0,x1,g_gfin[lane*2],g_gfin[lane*2+1],y0,y1);
    g_h[row*D+lane*2]   = (int8_t)y0;
    g_h[row*D+lane*2+1] = (int8_t)y1;
}

// ---------------- fused rmsnorm + QKV: 8 tokens per block ----------------
__global__ __launch_bounds__(256) void qkv_norm_kernel(int layer){
    __shared__ int sh[8*16];
    int tid = threadIdx.x, warp = tid>>5, lane = tid&31;
    int tok = blockIdx.x*8 + warp;
    {
        const int8_t* xr = g_x + tok*D;
        int x0 = xr[2*lane], x1 = xr[2*lane+1];
        const int* gm = g_gattn + layer*D;
        int y0,y1;
        rms_pair(x0,x1,gm[2*lane],gm[2*lane+1],y0,y1);
        uint8_t* hb = (uint8_t*)sh + warp*64;
        hb[2*lane]   = (uint8_t)(y0 & 0xff);
        hb[2*lane+1] = (uint8_t)(y1 & 0xff);
    }
    __syncthreads();
    if(tid < 192){
        int sel = tid>>6, o = tid&63;
        const int8_t* wb = (sel==0 ? g_wq : (sel==1 ? g_wk : g_wv)) + layer*D*D + o*D;
        const int* w = (const int*)wb;
        int wr[16];
        #pragma unroll
        for(int i=0;i<16;i++) wr[i] = w[i];
        int8_t* dst = (sel==0 ? g_q : (sel==1 ? g_k : g_v));
        #pragma unroll
        for(int t=0;t<8;t++){
            int acc = 0;
            #pragma unroll
            for(int i=0;i<16;i++) acc = __dp4a(sh[t*16+i], wr[i], acc);
            dst[(blockIdx.x*8+t)*D + o] = (int8_t)clampi(acc>>6,-128,127);
        }
    }
}

// ---------------- fused attention: scores + softmax + AV ----------------
// dyn smem: sK (T*9 words) | sVT (T/4*32 words) | sP (8 warps * 1024 B)
#define ATTN_SMEM ((T*9 + (T/4)*32)*4 + 8*T)
__global__ __launch_bounds__(256) void attn_fused_kernel(){
    extern __shared__ unsigned dyn[];
    unsigned* sK  = dyn;                    // 9216 words
    unsigned* sVT = dyn + T*9;              // 8192 words
    uint8_t*  sP  = (uint8_t*)(dyn + T*9 + (T/4)*32);
    int bh = blockIdx.y; int b = bh>>1, h = bh&1;
    int warp = threadIdx.x>>5, lane = threadIdx.x&31;

    const unsigned* kb = (const unsigned*)g_k + (b*T)*16 + h*8;
    const unsigned* vb = (const unsigned*)g_v + (b*T)*16 + h*8;
    uint8_t* svb = (uint8_t*)sVT;
    for(int idx=threadIdx.x; idx<T*8; idx+=256){
        int k = idx>>3, w = idx&7;
        sK[k*9+w] = kb[k*16+w];
        unsigned u = vb[k*16+w];
        int c = k>>2, r = k&3, d0 = w*4;
        svb[c*128 + (d0+0)*4 + r] = (uint8_t)( u        & 0xff);
        svb[c*128 + (d0+1)*4 + r] = (uint8_t)((u >> 8)  & 0xff);
        svb[c*128 + (d0+2)*4 + r] = (uint8_t)((u >> 16) & 0xff);
        svb[c*128 + (d0+3)*4 + r] = (uint8_t)((u >> 24) & 0xff);
    }
    __syncthreads();

    int q = blockIdx.x*8 + warp;
    const unsigned* qv = (const unsigned*)g_q + (b*T+q)*16 + h*8;
    unsigned qr[8];
    #pragma unroll
    for(int w=0;w<8;w++) qr[w] = qv[w];

    int jmax = q>>5;
    const int NEG = (int)0x80000000;
    int sc[32];
    int mx = NEG;
    #pragma unroll
    for(int j=0;j<32;j++){
        sc[j] = NEG;
        if(j <= jmax){
            int k = j*32 + lane;
            if(k <= q){
                int acc = 0;
                #pragma unroll
                for(int w=0;w<8;w++) acc = __dp4a((int)qr[w], (int)sK[k*9+w], acc);
                float p = __fmul_rn((float)acc, 45.f);
                int s = (int)floorf(__fmul_rn(p, 0.00390625f));
                sc[j] = s; mx = max(mx, s);
            }
        }
    }
    #pragma unroll
    for(int o=16;o>0;o>>=1) mx = max(mx, __shfl_xor_sync(0xffffffffu, mx, o));

    int su = 0;
    #pragma unroll
    for(int j=0;j<32;j++){
        if(sc[j] != NEG){
            int sh = sc[j] - mx;
            int ea = (sh>=-3) ? 256 + sh*64
                   : (sh>=-8) ? 64 + (sh+3)*11
                   : (sh>=-24)? sh + 24 : 0;
            sc[j] = ea; su += ea;
        } else sc[j] = 0;
    }
    #pragma unroll
    for(int o=16;o>0;o>>=1) su += __shfl_xor_sync(0xffffffffu, su, o);
    float sf = (float)max(su, 1);

    uint8_t* prow = sP + warp*T;
    #pragma unroll
    for(int j=0;j<32;j++){
        if(j <= jmax){
            int p = 0;
            if(sc[j] > 0)
                p = clampi((int)rintf(__fmul_rn(__fdiv_rn((float)sc[j], sf), 255.f)), 0, 255);
            prow[j*32+lane] = (uint8_t)p;
        }
    }
    __syncwarp();

    // AV: lane = head dim, dp4a over packed prob/V chunks
    const unsigned* pw = (const unsigned*)prow;
    int d = lane;
    int cmax = q>>2;
    int acc = 0;
    int c = 0;
    for(; c+4 <= cmax+1; c+=4){
        unsigned p0=pw[c], p1=pw[c+1], p2=pw[c+2], p3=pw[c+3];
        acc = dp4a_su((int)sVT[(c+0)*32+d], p0, acc);
        acc = dp4a_su((int)sVT[(c+1)*32+d], p1, acc);
        acc = dp4a_su((int)sVT[(c+2)*32+d], p2, acc);
        acc = dp4a_su((int)sVT[(c+3)*32+d], p3, acc);
    }
    for(; c<=cmax; c++)
        acc = dp4a_su((int)sVT[c*32+d], pw[c], acc);

    g_a[(b*T+q)*D + h*HD + d] = (int8_t)wrap8(acc>>8);
}

// ---------------- fused oproj + residual + rmsnorm + FFN + residual ----------------
__global__ __launch_bounds__(256) void ffn_fused_kernel(int layer){
    __shared__ int sa[16];
    __shared__ int sx[64];
    __shared__ int sh[16];
    __shared__ uint8_t su8[256];
    __shared__ int sred[256];
    int bt = blockIdx.x, tid = threadIdx.x;

    if(tid < 16) sa[tid] = ((const int*)g_a)[bt*16 + tid];
    __syncthreads();

    {   // oproj partials: all 256 threads (o = tid&63, seg = tid>>6)
        int o = tid&63, seg = tid>>6;
        const int* w = (const int*)(g_wo + layer*D*D) + o*16 + seg*4;
        int acc = 0;
        #pragma unroll
        for(int i=0;i<4;i++) acc = __dp4a(sa[seg*4+i], w[i], acc);
        sred[tid] = acc;
    }
    __syncthreads();
    if(tid < 64){
        int acc = sred[tid]+sred[tid+64]+sred[tid+128]+sred[tid+192];
        int r = clampi(acc>>6,-128,127);
        sx[tid] = wrap8((int)g_x[bt*D+tid] + r);
    }
    __syncthreads();

    if(tid < 32){
        int l = tid;
        int x0 = sx[2*l], x1 = sx[2*l+1];
        const int* gm = g_gff + layer*D;
        int y0,y1;
        rms_pair(x0,x1,gm[2*l],gm[2*l+1],y0,y1);
        uint8_t* hb = (uint8_t*)sh;
        hb[2*l]   = (uint8_t)(y0 & 0xff);
        hb[2*l+1] = (uint8_t)(y1 & 0xff);
    }
    __syncthreads();

    {   // up + relu: all 256 threads
        const int* w = (const int*)(g_wup + layer*DFF*D) + tid*16;
        int acc = 0;
        #pragma unroll
        for(int i=0;i<16;i++) acc = __dp4a(sh[i], w[i], acc);
        int u = clampi(acc>>6,-128,127);
        su8[tid] = (uint8_t)max(u,0);
    }
    __syncthreads();

    {   // down partials: all 256 threads (o = tid&63, seg = tid>>6, 16 words each)
        int o = tid&63, seg = tid>>6;
        const int* w = (const int*)(g_wdn + layer*D*DFF) + o*64 + seg*16;
        const int* suw = (const int*)su8 + seg*16;
        int acc = 0;
        #pragma unroll
        for(int i=0;i<16;i++) acc = __dp4a(suw[i], w[i], acc);
        sred[tid] = acc;
    }
    __syncthreads();
    if(tid < 64){
        int acc = sred[tid]+sred[tid+64]+sred[tid+128]+sred[tid+192];
        int r = clampi(acc>>6,-128,127);
        g_x[bt*D+tid] = (int8_t)wrap8(sx[tid] + r);
    }
}

// ---------------- logits via IMMA: warp = 64 tokens x 32 vocab ----------------
__global__ __launch_bounds__(256) void logits_mma_kernel(float* __restrict__ out){
    int warp = threadIdx.x>>5, lane = threadIdx.x&31;
    int g = lane>>2, tg = lane&3;
    int vbase = blockIdx.x*256 + warp*32;
    int mbase = blockIdx.y*64;

    // B fragments (emb hi/lo), reused over 4 M-subtiles
    int bhi[4][2][2], blo[4][2][2];
    #pragma unroll
    for(int nt=0;nt<4;nt++){
        int col = vbase + nt*8 + g;
        const int8_t*  eh = g_ehi + col*64;
        const uint8_t* el = g_elo + col*64;
        #pragma unroll
        for(int kc=0;kc<2;kc++){
            bhi[nt][kc][0] = *(const int*)(eh + kc*32 + tg*4);
            bhi[nt][kc][1] = *(const int*)(eh + kc*32 + 16 + tg*4);
            blo[nt][kc][0] = *(const int*)(el + kc*32 + tg*4);
            blo[nt][kc][1] = *(const int*)(el + kc*32 + 16 + tg*4);
        }
    }
    #pragma unroll
    for(int mt=0;mt<4;mt++){
        int row0 = mbase + mt*16 + g;
        const int8_t* h0 = g_h + row0*64;
        const int8_t* h8 = g_h + (row0+8)*64;
        int a[2][4];
        #pragma unroll
        for(int kc=0;kc<2;kc++){
            a[kc][0] = *(const int*)(h0 + kc*32 + tg*4);
            a[kc][1] = *(const int*)(h8 + kc*32 + tg*4);
            a[kc][2] = *(const int*)(h0 + kc*32 + 16 + tg*4);
            a[kc][3] = *(const int*)(h8 + kc*32 + 16 + tg*4);
        }
        #pragma unroll
        for(int nt=0;nt<4;nt++){
            int dh[4]={0,0,0,0}, dl[4]={0,0,0,0};
            #pragma unroll
            for(int kc=0;kc<2;kc++){
                mma_s8s8(dh, a[kc], bhi[nt][kc]);
                mma_s8u8(dl, a[kc], blo[nt][kc]);
            }
            int col = vbase + nt*8 + 2*tg;
            float2 v0, v1;
            v0.x = __fmul_rn((float)(dh[0]*256+dl[0]), 1.220703125e-4f);
            v0.y = __fmul_rn((float)(dh[1]*256+dl[1]), 1.220703125e-4f);
            v1.x = __fmul_rn((float)(dh[2]*256+dl[2]), 1.220703125e-4f);
            v1.y = __fmul_rn((float)(dh[3]*256+dl[3]), 1.220703125e-4f);
            *(float2*)(out + (size_t)row0*VOCAB + col)     = v0;
            *(float2*)(out + (size_t)(row0+8)*VOCAB + col) = v1;
        }
    }
}

// ---------------- launch ----------------
extern "C" void kernel_launch(void* const* d_in, const int* in_sizes, int n_in,
                              void* d_out, int out_size){
    const int*   tokens  = (const int*)  d_in[0];
    const float* tok_emb = (const float*)d_in[1];
    const float* pos_emb = (const float*)d_in[2];
    const float* attn_nw = (const float*)d_in[3];
    const float* qw      = (const float*)d_in[4];
    const float* kw      = (const float*)d_in[5];
    const float* vw      = (const float*)d_in[6];
    const float* ow      = (const float*)d_in[7];
    const float* ff_nw   = (const float*)d_in[8];
    const float* up      = (const float*)d_in[9];
    const float* dn      = (const float*)d_in[10];
    const float* fin_nw  = (const float*)d_in[11];
    float* out = (float*)d_out;

    cudaFuncSetAttribute(attn_fused_kernel,
                         cudaFuncAttributeMaxDynamicSharedMemorySize, ATTN_SMEM);

    quant_weights<<<24,256>>>(qw,kw,vw,ow,up,dn);
    prep_emb<<<(VOCAB*D+255)/256,256>>>(tok_emb, attn_nw, ff_nw, fin_nw);
    embed_kernel<<<(BT*D+255)/256,256>>>(tokens, tok_emb, pos_emb);

    for(int l=0;l<NL;l++){
        qkv_norm_kernel<<<BT/8,256>>>(l);
        attn_fused_kernel<<<dim3(T/8, BATCH*H),256,ATTN_SMEM>>>();
        ffn_fused_kernel<<<BT,256>>>(l);
    }
    rmsnorm_final_kernel<<<BT/8,256>>>();
    logits_mma_kernel<<<dim3(VOCAB/256, BT/64),256>>>(out);
}

// round 5
// speedup vs baseline: 6.9693x; 1.0542x over previous
#include <cuda_runtime.h>
#include <cstdint>

#define BATCH 4
#define T 1024
#define D 64
#define H 2
#define HD 32
#define DFF 256
#define NL 4
#define VOCAB 8192
#define BT (BATCH*T)

// ---------------- device scratch (no allocs allowed) ----------------
__device__ __align__(16) int8_t  g_x[BT*D];
__device__ __align__(16) int8_t  g_h[BT*D];
__device__ __align__(16) int8_t  g_q[BT*D];
__device__ __align__(16) int8_t  g_k[BT*D];
__device__ __align__(16) int8_t  g_v[BT*D];
__device__ __align__(16) int8_t  g_a[BT*D];
__device__ __align__(16) int8_t  g_wq[NL*D*D], g_wk[NL*D*D], g_wv[NL*D*D], g_wo[NL*D*D];
__device__ __align__(16) int8_t  g_wup[NL*DFF*D], g_wdn[NL*D*DFF];
__device__ __align__(16) int     g_gattn[NL*D], g_gff[NL*D], g_gfin[D];
__device__ __align__(16) int8_t  g_ehi[VOCAB*D];
__device__ __align__(16) uint8_t g_elo[VOCAB*D];

// ---------------- helpers ----------------
__device__ __forceinline__ int wrap8(int v){ return (int)(signed char)(v & 0xff); }
__device__ __forceinline__ int clampi(int v,int lo,int hi){ return min(max(v,lo),hi); }
__device__ __forceinline__ int dp4a_su(int a, unsigned b, int c){
    int r; asm("dp4a.s32.u32 %0,%1,%2,%3;" : "=r"(r) : "r"(a),"r"(b),"r"(c)); return r;
}
__device__ __forceinline__ int gammaq(float w){
    float c = fminf(fmaxf(w,-2.f),2.f);
    float r = rintf(__fmul_rn(c,1024.f));
    return clampi((int)r,-32768,32767);
}
__device__ __forceinline__ void rms_pair(int x0,int x1,int g0,int g1,int& y0,int& y1){
    int ss = x0*x0 + x1*x1;
    #pragma unroll
    for(int o=16;o>0;o>>=1) ss += __shfl_xor_sync(0xffffffffu, ss, o);
    int mean_sq = ss >> 6;
    int lut = min(mean_sq >> 6, 255);
    float bc = (float)(lut*64 + 32);
    int inv = clampi((int)rintf(__fdiv_rn(16384.f, __fsqrt_rn(bc))), 0, 16383);
    int p0 = (x0*inv) >> 8, p1 = (x1*inv) >> 8;
    y0 = clampi((int)floorf(__fmul_rn(__fmul_rn((float)p0,(float)g0), 0.0009765625f)),-128,127);
    y1 = clampi((int)floorf(__fmul_rn(__fmul_rn((float)p1,(float)g1), 0.0009765625f)),-128,127);
}
// m16n8k32 int8 MMA
__device__ __forceinline__ void mma_s8s8(int* d, const int* a, const int* b){
    asm("mma.sync.aligned.m16n8k32.row.col.s32.s8.s8.s32 "
        "{%0,%1,%2,%3},{%4,%5,%6,%7},{%8,%9},{%0,%1,%2,%3};"
        : "+r"(d[0]),"+r"(d[1]),"+r"(d[2]),"+r"(d[3])
        : "r"(a[0]),"r"(a[1]),"r"(a[2]),"r"(a[3]),"r"(b[0]),"r"(b[1]));
}
__device__ __forceinline__ void mma_s8u8(int* d, const int* a, const int* b){
    asm("mma.sync.aligned.m16n8k32.row.col.s32.s8.u8.s32 "
        "{%0,%1,%2,%3},{%4,%5,%6,%7},{%8,%9},{%0,%1,%2,%3};"
        : "+r"(d[0]),"+r"(d[1]),"+r"(d[2]),"+r"(d[3])
        : "r"(a[0]),"r"(a[1]),"r"(a[2]),"r"(a[3]),"r"(b[0]),"r"(b[1]));
}

// ---------------- weight ternarization ----------------
__global__ void quant_weights(const float* qw, const float* kw, const float* vw,
                              const float* ow, const float* up, const float* dn){
    int m = blockIdx.x; const float* src; int8_t* dst; int n;
    if(m < 16){
        int l = m >> 2, wsel = m & 3; n = D*D;
        const float* bases[4] = {qw,kw,vw,ow};
        int8_t* dsts[4] = {g_wq,g_wk,g_wv,g_wo};
        src = bases[wsel] + l*n; dst = dsts[wsel] + l*n;
    } else if(m < 20){ int l=m-16; n=DFF*D; src=up+l*n; dst=g_wup+l*n; }
    else             { int l=m-20; n=D*DFF; src=dn+l*n; dst=g_wdn+l*n; }

    __shared__ float red[256];
    float s = 0.f;
    for(int i=threadIdx.x;i<n;i+=256) s += fabsf(src[i]);
    red[threadIdx.x]=s; __syncthreads();
    for(int o=128;o>0;o>>=1){ if(threadIdx.x<o) red[threadIdx.x]+=red[threadIdx.x+o]; __syncthreads(); }
    float scale = fmaxf(__fdiv_rn(red[0], (float)n), 1e-5f);
    for(int i=threadIdx.x;i<n;i+=256){
        float t = rintf(__fdiv_rn(src[i], scale));
        t = fminf(fmaxf(t,-1.f),1.f);
        dst[i] = (int8_t)(int)t;
    }
}

// ---------------- embedding quant (hi/lo split) + gamma quant ----------------
__global__ void prep_emb(const float* tok_emb, const float* attn_nw,
                         const float* ff_nw, const float* fin_nw){
    int i = blockIdx.x*256 + threadIdx.x;
    if(i < VOCAB*D){
        float r = rintf(__fmul_rn(tok_emb[i],1024.f));
        int q = clampi((int)r,-32768,32767);
        g_ehi[i] = (int8_t)(q >> 8);
        g_elo[i] = (uint8_t)(q & 0xff);
    }
    if(blockIdx.x==0){
        int t=threadIdx.x;
        for(int j=t;j<NL*D;j+=256){
            g_gattn[j] = gammaq(attn_nw[j]);
            g_gff[j]   = gammaq(ff_nw[j]);
        }
        if(t<D) g_gfin[t] = gammaq(fin_nw[t]);
    }
}

// ---------------- token+pos embedding ----------------
__global__ void embed_kernel(const int* tokens, const float* tok_emb, const float* pos_emb){
    int i = blockIdx.x*256 + threadIdx.x;
    if(i >= BT*D) return;
    int bt = i >> 6, d = i & 63;
    int t = bt & (T-1);
    int tok = tokens[bt];
    int tq = clampi((int)rintf(__fmul_rn(tok_emb[tok*D+d],1024.f)),-32768,32767);
    int pq = clampi((int)rintf(__fmul_rn(pos_emb[t*D+d],1024.f)),-32768,32767);
    g_x[i] = (int8_t)wrap8((tq+pq) >> 3);
}

// ---------------- final rmsnorm (x -> g_h), one warp per row ----------------
__global__ void rmsnorm_final_kernel(){
    int row  = (blockIdx.x*blockDim.x + threadIdx.x) >> 5;
    int lane = threadIdx.x & 31;
    if(row >= BT) return;
    const int8_t* r = g_x + row*D;
    int x0 = r[lane*2], x1 = r[lane*2+1];
    int y0,y1;
    rms_pair(x0,x1,g_gfin[lane*2],g_gfin[lane*2+1],y0,y1);
    g_h[row*D+lane*2]   = (int8_t)y0;
    g_h[row*D+lane*2+1] = (int8_t)y1;
}

// ---------------- fused rmsnorm + QKV: 4 tokens per block, 192 threads ----------------
__global__ __launch_bounds__(192) void qkv_norm_kernel(int layer){
    __shared__ int sh[4*16];
    int tid = threadIdx.x, warp = tid>>5, lane = tid&31;
    if(warp < 4){
        int tok = blockIdx.x*4 + warp;
        const int8_t* xr = g_x + tok*D;
        int x0 = xr[2*lane], x1 = xr[2*lane+1];
        const int* gm = g_gattn + layer*D;
        int y0,y1;
        rms_pair(x0,x1,gm[2*lane],gm[2*lane+1],y0,y1);
        uint8_t* hb = (uint8_t*)sh + warp*64;
        hb[2*lane]   = (uint8_t)(y0 & 0xff);
        hb[2*lane+1] = (uint8_t)(y1 & 0xff);
    }
    __syncthreads();
    {
        int sel = tid>>6, o = tid&63;   // 192 = 3*64 exactly
        const int8_t* wb = (sel==0 ? g_wq : (sel==1 ? g_wk : g_wv)) + layer*D*D + o*D;
        const int* w = (const int*)wb;
        int wr[16];
        #pragma unroll
        for(int i=0;i<16;i++) wr[i] = w[i];
        int8_t* dst = (sel==0 ? g_q : (sel==1 ? g_k : g_v));
        #pragma unroll
        for(int t=0;t<4;t++){
            int acc = 0;
            #pragma unroll
            for(int i=0;i<16;i++) acc = __dp4a(sh[t*16+i], wr[i], acc);
            dst[(blockIdx.x*4+t)*D + o] = (int8_t)clampi(acc>>6,-128,127);
        }
    }
}

// ---------------- fused attention: scores + softmax + AV ----------------
// dyn smem: sK (T*8 words, XOR-swizzled) | sVT (T/4*32 words) | sP (8 warps * 1024 B) = 72KB
#define ATTN_SMEM ((T*8 + (T/4)*32)*4 + 8*T)
__device__ __forceinline__ int ksw(int k,int w){ return k*8 + (w ^ ((k>>2)&7)); }

__global__ __launch_bounds__(256,3) void attn_fused_kernel(){
    extern __shared__ unsigned dyn[];
    unsigned* sK  = dyn;                    // 8192 words, swizzled
    unsigned* sVT = dyn + T*8;              // 8192 words
    uint8_t*  sP  = (uint8_t*)(dyn + T*8 + (T/4)*32);
    int bh = blockIdx.y; int b = bh>>1, h = bh&1;
    int warp = threadIdx.x>>5, lane = threadIdx.x&31;

    // only stage keys this q-tile can see (rounded up to 32)
    int KN = min(T, (((blockIdx.x*8+7)>>5)+1)*32);

    const unsigned* kb = (const unsigned*)g_k + (b*T)*16 + h*8;
    const unsigned* vb = (const unsigned*)g_v + (b*T)*16 + h*8;
    uint8_t* svb = (uint8_t*)sVT;
    for(int idx=threadIdx.x; idx<KN*8; idx+=256){
        int k = idx>>3, w = idx&7;
        sK[ksw(k,w)] = kb[k*16+w];
        unsigned u = vb[k*16+w];
        int c = k>>2, r = k&3, d0 = w*4;
        svb[c*128 + (d0+0)*4 + r] = (uint8_t)( u        & 0xff);
        svb[c*128 + (d0+1)*4 + r] = (uint8_t)((u >> 8)  & 0xff);
        svb[c*128 + (d0+2)*4 + r] = (uint8_t)((u >> 16) & 0xff);
        svb[c*128 + (d0+3)*4 + r] = (uint8_t)((u >> 24) & 0xff);
    }
    __syncthreads();

    int q = blockIdx.x*8 + warp;
    const unsigned* qv = (const unsigned*)g_q + (b*T+q)*16 + h*8;
    unsigned qr[8];
    #pragma unroll
    for(int w=0;w<8;w++) qr[w] = qv[w];

    int jmax = q>>5;
    const int NEG = (int)0x80000000;
    int sc[32];
    int mx = NEG;
    #pragma unroll
    for(int j=0;j<32;j++){
        sc[j] = NEG;
        if(j <= jmax){
            int k = j*32 + lane;
            if(k <= q){
                int acc = 0;
                #pragma unroll
                for(int w=0;w<8;w++) acc = __dp4a((int)qr[w], (int)sK[ksw(k,w)], acc);
                float p = __fmul_rn((float)acc, 45.f);
                int s = (int)floorf(__fmul_rn(p, 0.00390625f));
                sc[j] = s; mx = max(mx, s);
            }
        }
    }
    #pragma unroll
    for(int o=16;o>0;o>>=1) mx = max(mx, __shfl_xor_sync(0xffffffffu, mx, o));

    int su = 0;
    #pragma unroll
    for(int j=0;j<32;j++){
        if(sc[j] != NEG){
            int sh = sc[j] - mx;
            int ea = (sh>=-3) ? 256 + sh*64
                   : (sh>=-8) ? 64 + (sh+3)*11
                   : (sh>=-24)? sh + 24 : 0;
            sc[j] = ea; su += ea;
        } else sc[j] = 0;
    }
    #pragma unroll
    for(int o=16;o>0;o>>=1) su += __shfl_xor_sync(0xffffffffu, su, o);
    float sf = (float)max(su, 1);

    uint8_t* prow = sP + warp*T;
    #pragma unroll
    for(int j=0;j<32;j++){
        if(j <= jmax){
            int p = 0;
            if(sc[j] > 0)
                p = clampi((int)rintf(__fmul_rn(__fdiv_rn((float)sc[j], sf), 255.f)), 0, 255);
            prow[j*32+lane] = (uint8_t)p;
        }
    }
    __syncwarp();

    // AV: lane = head dim, dp4a over packed prob/V chunks; 4 indep accumulators
    const unsigned* pw = (const unsigned*)prow;
    int d = lane;
    int cmax = q>>2;
    int a0=0,a1=0,a2=0,a3=0;
    int c = 0;
    for(; c+4 <= cmax+1; c+=4){
        a0 = dp4a_su((int)sVT[(c+0)*32+d], pw[c+0], a0);
        a1 = dp4a_su((int)sVT[(c+1)*32+d], pw[c+1], a1);
        a2 = dp4a_su((int)sVT[(c+2)*32+d], pw[c+2], a2);
        a3 = dp4a_su((int)sVT[(c+3)*32+d], pw[c+3], a3);
    }
    for(; c<=cmax; c++)
        a0 = dp4a_su((int)sVT[c*32+d], pw[c], a0);
    int acc = (a0+a1)+(a2+a3);

    g_a[(b*T+q)*D + h*HD + d] = (int8_t)wrap8(acc>>8);
}

// ---------------- fused oproj + residual + rmsnorm + FFN + residual ----------------
__global__ __launch_bounds__(256) void ffn_fused_kernel(int layer){
    __shared__ int sa[16];
    __shared__ int sx[64];
    __shared__ int sh[16];
    __shared__ uint8_t su8[256];
    __shared__ int sred[256];
    int bt = blockIdx.x, tid = threadIdx.x;

    if(tid < 16) sa[tid] = ((const int*)g_a)[bt*16 + tid];
    __syncthreads();

    {   // oproj partials
        int o = tid&63, seg = tid>>6;
        const int* w = (const int*)(g_wo + layer*D*D) + o*16 + seg*4;
        int acc = 0;
        #pragma unroll
        for(int i=0;i<4;i++) acc = __dp4a(sa[seg*4+i], w[i], acc);
        sred[tid] = acc;
    }
    __syncthreads();
    if(tid < 64){
        int acc = sred[tid]+sred[tid+64]+sred[tid+128]+sred[tid+192];
        int r = clampi(acc>>6,-128,127);
        sx[tid] = wrap8((int)g_x[bt*D+tid] + r);
    }
    __syncthreads();

    if(tid < 32){
        int l = tid;
        int x0 = sx[2*l], x1 = sx[2*l+1];
        const int* gm = g_gff + layer*D;
        int y0,y1;
        rms_pair(x0,x1,gm[2*l],gm[2*l+1],y0,y1);
        uint8_t* hb = (uint8_t*)sh;
        hb[2*l]   = (uint8_t)(y0 & 0xff);
        hb[2*l+1] = (uint8_t)(y1 & 0xff);
    }
    __syncthreads();

    {   // up + relu
        const int* w = (const int*)(g_wup + layer*DFF*D) + tid*16;
        int acc = 0;
        #pragma unroll
        for(int i=0;i<16;i++) acc = __dp4a(sh[i], w[i], acc);
        int u = clampi(acc>>6,-128,127);
        su8[tid] = (uint8_t)max(u,0);
    }
    __syncthreads();

    {   // down partials
        int o = tid&63, seg = tid>>6;
        const int* w = (const int*)(g_wdn + layer*D*DFF) + o*64 + seg*16;
        const int* suw = (const int*)su8 + seg*16;
        int acc = 0;
        #pragma unroll
        for(int i=0;i<16;i++) acc = __dp4a(suw[i], w[i], acc);
        sred[tid] = acc;
    }
    __syncthreads();
    if(tid < 64){
        int acc = sred[tid]+sred[tid+64]+sred[tid+128]+sred[tid+192];
        int r = clampi(acc>>6,-128,127);
        g_x[bt*D+tid] = (int8_t)wrap8(sx[tid] + r);
    }
}

// ---------------- logits via IMMA: warp = 64 tokens x 32 vocab ----------------
__global__ __launch_bounds__(256) void logits_mma_kernel(float* __restrict__ out){
    int warp = threadIdx.x>>5, lane = threadIdx.x&31;
    int g = lane>>2, tg = lane&3;
    int vbase = blockIdx.x*256 + warp*32;
    int mbase = blockIdx.y*64;

    int bhi[4][2][2], blo[4][2][2];
    #pragma unroll
    for(int nt=0;nt<4;nt++){
        int col = vbase + nt*8 + g;
        const int8_t*  eh = g_ehi + col*64;
        const uint8_t* el = g_elo + col*64;
        #pragma unroll
        for(int kc=0;kc<2;kc++){
            bhi[nt][kc][0] = *(const int*)(eh + kc*32 + tg*4);
            bhi[nt][kc][1] = *(const int*)(eh + kc*32 + 16 + tg*4);
            blo[nt][kc][0] = *(const int*)(el + kc*32 + tg*4);
            blo[nt][kc][1] = *(const int*)(el + kc*32 + 16 + tg*4);
        }
    }
    #pragma unroll
    for(int mt=0;mt<4;mt++){
        int row0 = mbase + mt*16 + g;
        const int8_t* h0 = g_h + row0*64;
        const int8_t* h8 = g_h + (row0+8)*64;
        int a[2][4];
        #pragma unroll
        for(int kc=0;kc<2;kc++){
            a[kc][0] = *(const int*)(h0 + kc*32 + tg*4);
            a[kc][1] = *(const int*)(h8 + kc*32 + tg*4);
            a[kc][2] = *(const int*)(h0 + kc*32 + 16 + tg*4);
            a[kc][3] = *(const int*)(h8 + kc*32 + 16 + tg*4);
        }
        #pragma unroll
        for(int nt=0;nt<4;nt++){
            int dh[4]={0,0,0,0}, dl[4]={0,0,0,0};
            #pragma unroll
            for(int kc=0;kc<2;kc++){
                mma_s8s8(dh, a[kc], bhi[nt][kc]);
                mma_s8u8(dl, a[kc], blo[nt][kc]);
            }
            int col = vbase + nt*8 + 2*tg;
            float2 v0, v1;
            v0.x = __fmul_rn((float)(dh[0]*256+dl[0]), 1.220703125e-4f);
            v0.y = __fmul_rn((float)(dh[1]*256+dl[1]), 1.220703125e-4f);
            v1.x = __fmul_rn((float)(dh[2]*256+dl[2]), 1.220703125e-4f);
            v1.y = __fmul_rn((float)(dh[3]*256+dl[3]), 1.220703125e-4f);
            *(float2*)(out + (size_t)row0*VOCAB + col)     = v0;
            *(float2*)(out + (size_t)(row0+8)*VOCAB + col) = v1;
        }
    }
}

// ---------------- launch ----------------
extern "C" void kernel_launch(void* const* d_in, const int* in_sizes, int n_in,
                              void* d_out, int out_size){
    const int*   tokens  = (const int*)  d_in[0];
    const float* tok_emb = (const float*)d_in[1];
    const float* pos_emb = (const float*)d_in[2];
    const float* attn_nw = (const float*)d_in[3];
    const float* qw      = (const float*)d_in[4];
    const float* kw      = (const float*)d_in[5];
    const float* vw      = (const float*)d_in[6];
    const float* ow      = (const float*)d_in[7];
    const float* ff_nw   = (const float*)d_in[8];
    const float* up      = (const float*)d_in[9];
    const float* dn      = (const float*)d_in[10];
    const float* fin_nw  = (const float*)d_in[11];
    float* out = (float*)d_out;

    cudaFuncSetAttribute(attn_fused_kernel,
                         cudaFuncAttributeMaxDynamicSharedMemorySize, ATTN_SMEM);

    quant_weights<<<24,256>>>(qw,kw,vw,ow,up,dn);
    prep_emb<<<(VOCAB*D+255)/256,256>>>(tok_emb, attn_nw, ff_nw, fin_nw);
    embed_kernel<<<(BT*D+255)/256,256>>>(tokens, tok_emb, pos_emb);

    for(int l=0;l<NL;l++){
        qkv_norm_kernel<<<BT/4,192>>>(l);
        attn_fused_kernel<<<dim3(T/8, BATCH*H),256,ATTN_SMEM>>>();
        ffn_fused_kernel<<<BT,256>>>(l);
    }
    rmsnorm_final_kernel<<<BT/8,256>>>();
    logits_mma_kernel<<<dim3(VOCAB/256, BT/64),256>>>(out);
}

// round 6
// speedup vs baseline: 7.2035x; 1.0336x over previous
#include <cuda_runtime.h>
#include <cstdint>

#define BATCH 4
#define T 1024
#define D 64
#define H 2
#define HD 32
#define DFF 256
#define NL 4
#define VOCAB 8192
#define BT (BATCH*T)

// ---------------- device scratch (no allocs allowed) ----------------
__device__ __align__(16) int8_t  g_x[BT*D];
__device__ __align__(16) int8_t  g_h[BT*D];
__device__ __align__(16) int8_t  g_q[BT*D];
__device__ __align__(16) int8_t  g_k[BT*D];
__device__ __align__(16) int8_t  g_v[BT*D];
__device__ __align__(16) int8_t  g_a[BT*D];
__device__ __align__(16) int8_t  g_wq[NL*D*D], g_wk[NL*D*D], g_wv[NL*D*D], g_wo[NL*D*D];
__device__ __align__(16) int8_t  g_wup[NL*DFF*D], g_wdn[NL*D*DFF];
__device__ __align__(16) int     g_gattn[NL*D], g_gff[NL*D], g_gfin[D];
__device__ __align__(16) int8_t  g_ehi[VOCAB*D];
__device__ __align__(16) uint8_t g_elo[VOCAB*D];

// ---------------- helpers ----------------
__device__ __forceinline__ int wrap8(int v){ return (int)(signed char)(v & 0xff); }
__device__ __forceinline__ int clampi(int v,int lo,int hi){ return min(max(v,lo),hi); }
__device__ __forceinline__ int gammaq(float w){
    float c = fminf(fmaxf(w,-2.f),2.f);
    float r = rintf(__fmul_rn(c,1024.f));
    return clampi((int)r,-32768,32767);
}
__device__ __forceinline__ void rms_pair(int x0,int x1,int g0,int g1,int& y0,int& y1){
    int ss = x0*x0 + x1*x1;
    #pragma unroll
    for(int o=16;o>0;o>>=1) ss += __shfl_xor_sync(0xffffffffu, ss, o);
    int mean_sq = ss >> 6;
    int lut = min(mean_sq >> 6, 255);
    float bc = (float)(lut*64 + 32);
    int inv = clampi((int)rintf(__fdiv_rn(16384.f, __fsqrt_rn(bc))), 0, 16383);
    int p0 = (x0*inv) >> 8, p1 = (x1*inv) >> 8;
    y0 = clampi((int)floorf(__fmul_rn(__fmul_rn((float)p0,(float)g0), 0.0009765625f)),-128,127);
    y1 = clampi((int)floorf(__fmul_rn(__fmul_rn((float)p1,(float)g1), 0.0009765625f)),-128,127);
}
// m16n8k32 int8 MMA
__device__ __forceinline__ void mma_s8s8(int* d, const int* a, const int* b){
    asm("mma.sync.aligned.m16n8k32.row.col.s32.s8.s8.s32 "
        "{%0,%1,%2,%3},{%4,%5,%6,%7},{%8,%9},{%0,%1,%2,%3};"
        : "+r"(d[0]),"+r"(d[1]),"+r"(d[2]),"+r"(d[3])
        : "r"(a[0]),"r"(a[1]),"r"(a[2]),"r"(a[3]),"r"(b[0]),"r"(b[1]));
}
__device__ __forceinline__ void mma_s8u8(int* d, const int* a, const int* b){
    asm("mma.sync.aligned.m16n8k32.row.col.s32.s8.u8.s32 "
        "{%0,%1,%2,%3},{%4,%5,%6,%7},{%8,%9},{%0,%1,%2,%3};"
        : "+r"(d[0]),"+r"(d[1]),"+r"(d[2]),"+r"(d[3])
        : "r"(a[0]),"r"(a[1]),"r"(a[2]),"r"(a[3]),"r"(b[0]),"r"(b[1]));
}
__device__ __forceinline__ void mma_u8s8(int* d, const unsigned* a, const int* b){
    asm("mma.sync.aligned.m16n8k32.row.col.s32.u8.s8.s32 "
        "{%0,%1,%2,%3},{%4,%5,%6,%7},{%8,%9},{%0,%1,%2,%3};"
        : "+r"(d[0]),"+r"(d[1]),"+r"(d[2]),"+r"(d[3])
        : "r"(a[0]),"r"(a[1]),"r"(a[2]),"r"(a[3]),"r"(b[0]),"r"(b[1]));
}

// ---------------- weight ternarization ----------------
__global__ void quant_weights(const float* qw, const float* kw, const float* vw,
                              const float* ow, const float* up, const float* dn){
    int m = blockIdx.x; const float* src; int8_t* dst; int n;
    if(m < 16){
        int l = m >> 2, wsel = m & 3; n = D*D;
        const float* bases[4] = {qw,kw,vw,ow};
        int8_t* dsts[4] = {g_wq,g_wk,g_wv,g_wo};
        src = bases[wsel] + l*n; dst = dsts[wsel] + l*n;
    } else if(m < 20){ int l=m-16; n=DFF*D; src=up+l*n; dst=g_wup+l*n; }
    else             { int l=m-20; n=D*DFF; src=dn+l*n; dst=g_wdn+l*n; }

    __shared__ float red[256];
    float s = 0.f;
    for(int i=threadIdx.x;i<n;i+=256) s += fabsf(src[i]);
    red[threadIdx.x]=s; __syncthreads();
    for(int o=128;o>0;o>>=1){ if(threadIdx.x<o) red[threadIdx.x]+=red[threadIdx.x+o]; __syncthreads(); }
    float scale = fmaxf(__fdiv_rn(red[0], (float)n), 1e-5f);
    for(int i=threadIdx.x;i<n;i+=256){
        float t = rintf(__fdiv_rn(src[i], scale));
        t = fminf(fmaxf(t,-1.f),1.f);
        dst[i] = (int8_t)(int)t;
    }
}

// ---------------- embedding quant (hi/lo split) + gamma quant ----------------
__global__ void prep_emb(const float* tok_emb, const float* attn_nw,
                         const float* ff_nw, const float* fin_nw){
    int i = blockIdx.x*256 + threadIdx.x;
    if(i < VOCAB*D){
        float r = rintf(__fmul_rn(tok_emb[i],1024.f));
        int q = clampi((int)r,-32768,32767);
        g_ehi[i] = (int8_t)(q >> 8);
        g_elo[i] = (uint8_t)(q & 0xff);
    }
    if(blockIdx.x==0){
        int t=threadIdx.x;
        for(int j=t;j<NL*D;j+=256){
            g_gattn[j] = gammaq(attn_nw[j]);
            g_gff[j]   = gammaq(ff_nw[j]);
        }
        if(t<D) g_gfin[t] = gammaq(fin_nw[t]);
    }
}

// ---------------- token+pos embedding ----------------
__global__ void embed_kernel(const int* tokens, const float* tok_emb, const float* pos_emb){
    int i = blockIdx.x*256 + threadIdx.x;
    if(i >= BT*D) return;
    int bt = i >> 6, d = i & 63;
    int t = bt & (T-1);
    int tok = tokens[bt];
    int tq = clampi((int)rintf(__fmul_rn(tok_emb[tok*D+d],1024.f)),-32768,32767);
    int pq = clampi((int)rintf(__fmul_rn(pos_emb[t*D+d],1024.f)),-32768,32767);
    g_x[i] = (int8_t)wrap8((tq+pq) >> 3);
}

// ---------------- final rmsnorm (x -> g_h), one warp per row ----------------
__global__ void rmsnorm_final_kernel(){
    int row  = (blockIdx.x*blockDim.x + threadIdx.x) >> 5;
    int lane = threadIdx.x & 31;
    if(row >= BT) return;
    const int8_t* r = g_x + row*D;
    int x0 = r[lane*2], x1 = r[lane*2+1];
    int y0,y1;
    rms_pair(x0,x1,g_gfin[lane*2],g_gfin[lane*2+1],y0,y1);
    g_h[row*D+lane*2]   = (int8_t)y0;
    g_h[row*D+lane*2+1] = (int8_t)y1;
}

// ---------------- fused rmsnorm + QKV: 4 tokens per block, 192 threads ----------------
__global__ __launch_bounds__(192) void qkv_norm_kernel(int layer){
    __shared__ int sh[4*16];
    int tid = threadIdx.x, warp = tid>>5, lane = tid&31;
    if(warp < 4){
        int tok = blockIdx.x*4 + warp;
        const int8_t* xr = g_x + tok*D;
        int x0 = xr[2*lane], x1 = xr[2*lane+1];
        const int* gm = g_gattn + layer*D;
        int y0,y1;
        rms_pair(x0,x1,gm[2*lane],gm[2*lane+1],y0,y1);
        uint8_t* hb = (uint8_t*)sh + warp*64;
        hb[2*lane]   = (uint8_t)(y0 & 0xff);
        hb[2*lane+1] = (uint8_t)(y1 & 0xff);
    }
    __syncthreads();
    {
        int sel = tid>>6, o = tid&63;
        const int8_t* wb = (sel==0 ? g_wq : (sel==1 ? g_wk : g_wv)) + layer*D*D + o*D;
        const int* w = (const int*)wb;
        int wr[16];
        #pragma unroll
        for(int i=0;i<16;i++) wr[i] = w[i];
        int8_t* dst = (sel==0 ? g_q : (sel==1 ? g_k : g_v));
        #pragma unroll
        for(int t=0;t<4;t++){
            int acc = 0;
            #pragma unroll
            for(int i=0;i<16;i++) acc = __dp4a(sh[t*16+i], wr[i], acc);
            dst[(blockIdx.x*4+t)*D + o] = (int8_t)clampi(acc>>6,-128,127);
        }
    }
}

// ---------------- fused attention: scores + LUT softmax + MMA AV ----------------
#define SK_WORDS   (T*8)                   // swizzled K: 32768 B
#define SVT_PITCH  33                      // words per key-quad row (padded)
#define SVT_WORDS  ((T/4)*SVT_PITCH)       // 33792 B
#define SP_PITCH   1040                    // bytes per prob row (padded)
#define SP_BYTES   (8*SP_PITCH)            // 8320 B
#define ATTN_SMEM  ((SK_WORDS+SVT_WORDS)*4 + SP_BYTES + 256*4)
__device__ __forceinline__ int ksw(int k,int w){ return k*8 + (w ^ ((k>>2)&7)); }

__global__ __launch_bounds__(256) void attn_fused_kernel(){
    extern __shared__ unsigned dyn[];
    unsigned* sK  = dyn;
    unsigned* sVT = dyn + SK_WORDS;
    uint8_t*  sP  = (uint8_t*)(dyn + SK_WORDS + SVT_WORDS);
    int*      sred = (int*)(sP + SP_BYTES);
    int bh = blockIdx.y; int b = bh>>1, h = bh&1;
    int warp = threadIdx.x>>5, lane = threadIdx.x&31;
    int g = lane>>2, tg = lane&3;

    int jmaxb = (blockIdx.x*8+7)>>5;           // uniform over block (tiles 8-aligned)
    int KN = (jmaxb+1)*32;                      // keys to stage

    const unsigned* kb = (const unsigned*)g_k + (b*T)*16 + h*8;
    const unsigned* vb = (const unsigned*)g_v + (b*T)*16 + h*8;
    uint8_t* svb = (uint8_t*)sVT;
    for(int idx=threadIdx.x; idx<KN*8; idx+=256){
        int k = idx>>3, w = idx&7;
        sK[ksw(k,w)] = kb[k*16+w];
        unsigned u = vb[k*16+w];
        int c = k>>2, r = k&3, d0 = w*4;
        svb[c*(SVT_PITCH*4) + (d0+0)*4 + r] = (uint8_t)( u        & 0xff);
        svb[c*(SVT_PITCH*4) + (d0+1)*4 + r] = (uint8_t)((u >> 8)  & 0xff);
        svb[c*(SVT_PITCH*4) + (d0+2)*4 + r] = (uint8_t)((u >> 16) & 0xff);
        svb[c*(SVT_PITCH*4) + (d0+3)*4 + r] = (uint8_t)((u >> 24) & 0xff);
    }
    __syncthreads();

    // ---- per-warp: one query ----
    int q = blockIdx.x*8 + warp;
    const unsigned* qv = (const unsigned*)g_q + (b*T+q)*16 + h*8;
    unsigned qr[8];
    #pragma unroll
    for(int w=0;w<8;w++) qr[w] = qv[w];

    const int NEG = (int)0x80000000;
    int sc[32];
    int mx = NEG;
    #pragma unroll
    for(int j=0;j<32;j++){
        sc[j] = NEG;
        if(j <= jmaxb){
            int k = j*32 + lane;
            if(k <= q){
                int acc = 0;
                #pragma unroll
                for(int w=0;w<8;w++) acc = __dp4a((int)qr[w], (int)sK[ksw(k,w)], acc);
                // rn(acc*45) == fmul_rn((float)acc,45): acc exact in f32
                float p = __int2float_rn(acc*45);
                int s = (int)floorf(__fmul_rn(p, 0.00390625f));
                sc[j] = s; mx = max(mx, s);
            }
        }
    }
    #pragma unroll
    for(int o=16;o>0;o>>=1) mx = max(mx, __shfl_xor_sync(0xffffffffu, mx, o));

    // ea LUT: lane l holds ea(sh = l-24), l<=24
    int sh_l = lane - 24;
    int ea_l = (sh_l>=-3) ? 256 + sh_l*64
             : (sh_l>=-8) ? 64 + (sh_l+3)*11
             : sh_l + 24;
    if(lane > 24) ea_l = 0;

    int su = 0;
    #pragma unroll
    for(int j=0;j<32;j++){
        bool valid = (sc[j] != NEG);
        int idx = valid ? (sc[j] - mx + 24) : -1;   // <=24 when valid
        int idxc = clampi(idx, 0, 31);
        int ea = __shfl_sync(0xffffffffu, ea_l, idxc);
        if(!(valid && idx >= 0)) ea = 0;
        su += ea;
        sc[j] = (valid && idx >= 0) ? idx : 32;     // sentinel 32 -> p=0
    }
    #pragma unroll
    for(int o=16;o>0;o>>=1) su += __shfl_xor_sync(0xffffffffu, su, o);
    float sf = (float)max(su, 1);

    // prob LUT: one exact fdiv per lane per row (instead of per pair)
    int p_l = 0;
    if(ea_l > 0)
        p_l = clampi((int)rintf(__fmul_rn(__fdiv_rn((float)ea_l, sf), 255.f)), 0, 255);

    uint8_t* prow = sP + warp*SP_PITCH;
    #pragma unroll
    for(int j=0;j<32;j++){
        if(j <= jmaxb){                              // warp-uniform branch
            int idx = sc[j];
            int p = __shfl_sync(0xffffffffu, p_l, idx & 31);
            if(idx >= 32) p = 0;
            prow[j*32+lane] = (uint8_t)p;
        }
    }
    __syncthreads();

    // ---- AV via u8 x s8 MMA: warp (nt=warp&3 dim-tile, half=warp>>2 chunk parity) ----
    int nt = warp & 3, half = warp >> 2;
    int dim = nt*8 + g;
    int dacc[4] = {0,0,0,0};
    for(int c32 = half; c32 <= jmaxb; c32 += 2){
        const uint8_t* pr = sP + g*SP_PITCH + c32*32;
        unsigned A[4];
        A[0] = *(const unsigned*)(pr + tg*4);
        A[1] = A[0];                                // rows 8-15 garbage, discarded
        A[2] = *(const unsigned*)(pr + 16 + tg*4);
        A[3] = A[2];
        int Bv[2];
        Bv[0] = (int)sVT[(c32*8 + tg)*SVT_PITCH + dim];
        Bv[1] = (int)sVT[(c32*8 + 4 + tg)*SVT_PITCH + dim];
        mma_u8s8(dacc, A, Bv);
    }
    if(half == 1){
        sred[nt*64 + g*8 + 2*tg]     = dacc[0];
        sred[nt*64 + g*8 + 2*tg + 1] = dacc[1];
    }
    __syncthreads();
    if(half == 0){
        int v0 = dacc[0] + sred[nt*64 + g*8 + 2*tg];
        int v1 = dacc[1] + sred[nt*64 + g*8 + 2*tg + 1];
        int qq = blockIdx.x*8 + g;
        int o0 = wrap8(v0>>8) & 0xff, o1 = wrap8(v1>>8) & 0xff;
        *(uint16_t*)(g_a + (b*T+qq)*64 + h*32 + nt*8 + 2*tg) = (uint16_t)(o0 | (o1<<8));
    }
}

// ---------------- fused oproj + residual + rmsnorm + FFN + residual ----------------
__global__ __launch_bounds__(256) void ffn_fused_kernel(int layer){
    __shared__ int sa[16];
    __shared__ int sx[64];
    __shared__ int sh[16];
    __shared__ uint8_t su8[256];
    __shared__ int sred[256];
    int bt = blockIdx.x, tid = threadIdx.x;

    if(tid < 16) sa[tid] = ((const int*)g_a)[bt*16 + tid];
    __syncthreads();

    {   // oproj partials
        int o = tid&63, seg = tid>>6;
        const int* w = (const int*)(g_wo + layer*D*D) + o*16 + seg*4;
        int acc = 0;
        #pragma unroll
        for(int i=0;i<4;i++) acc = __dp4a(sa[seg*4+i], w[i], acc);
        sred[tid] = acc;
    }
    __syncthreads();
    if(tid < 64){
        int acc = sred[tid]+sred[tid+64]+sred[tid+128]+sred[tid+192];
        int r = clampi(acc>>6,-128,127);
        sx[tid] = wrap8((int)g_x[bt*D+tid] + r);
    }
    __syncthreads();

    if(tid < 32){
        int l = tid;
        int x0 = sx[2*l], x1 = sx[2*l+1];
        const int* gm = g_gff + layer*D;
        int y0,y1;
        rms_pair(x0,x1,gm[2*l],gm[2*l+1],y0,y1);
        uint8_t* hb = (uint8_t*)sh;
        hb[2*l]   = (uint8_t)(y0 & 0xff);
        hb[2*l+1] = (uint8_t)(y1 & 0xff);
    }
    __syncthreads();

    {   // up + relu
        const int* w = (const int*)(g_wup + layer*DFF*D) + tid*16;
        int acc = 0;
        #pragma unroll
        for(int i=0;i<16;i++) acc = __dp4a(sh[i], w[i], acc);
        int u = clampi(acc>>6,-128,127);
        su8[tid] = (uint8_t)max(u,0);
    }
    __syncthreads();

    {   // down partials
        int o = tid&63, seg = tid>>6;
        const int* w = (const int*)(g_wdn + layer*D*DFF) + o*64 + seg*16;
        const int* suw = (const int*)su8 + seg*16;
        int acc = 0;
        #pragma unroll
        for(int i=0;i<16;i++) acc = __dp4a(suw[i], w[i], acc);
        sred[tid] = acc;
    }
    __syncthreads();
    if(tid < 64){
        int acc = sred[tid]+sred[tid+64]+sred[tid+128]+sred[tid+192];
        int r = clampi(acc>>6,-128,127);
        g_x[bt*D+tid] = (int8_t)wrap8(sx[tid] + r);
    }
}

// ---------------- logits via IMMA: warp = 64 tokens x 32 vocab ----------------
__global__ __launch_bounds__(256) void logits_mma_kernel(float* __restrict__ out){
    int warp = threadIdx.x>>5, lane = threadIdx.x&31;
    int g = lane>>2, tg = lane&3;
    int vbase = blockIdx.x*256 + warp*32;
    int mbase = blockIdx.y*64;

    int bhi[4][2][2], blo[4][2][2];
    #pragma unroll
    for(int nt=0;nt<4;nt++){
        int col = vbase + nt*8 + g;
        const int8_t*  eh = g_ehi + col*64;
        const uint8_t* el = g_elo + col*64;
        #pragma unroll
        for(int kc=0;kc<2;kc++){
            bhi[nt][kc][0] = *(const int*)(eh + kc*32 + tg*4);
            bhi[nt][kc][1] = *(const int*)(eh + kc*32 + 16 + tg*4);
            blo[nt][kc][0] = *(const int*)(el + kc*32 + tg*4);
            blo[nt][kc][1] = *(const int*)(el + kc*32 + 16 + tg*4);
        }
    }
    #pragma unroll
    for(int mt=0;mt<4;mt++){
        int row0 = mbase + mt*16 + g;
        const int8_t* h0 = g_h + row0*64;
        const int8_t* h8 = g_h + (row0+8)*64;
        int a[2][4];
        #pragma unroll
        for(int kc=0;kc<2;kc++){
            a[kc][0] = *(const int*)(h0 + kc*32 + tg*4);
            a[kc][1] = *(const int*)(h8 + kc*32 + tg*4);
            a[kc][2] = *(const int*)(h0 + kc*32 + 16 + tg*4);
            a[kc][3] = *(const int*)(h8 + kc*32 + 16 + tg*4);
        }
        #pragma unroll
        for(int nt=0;nt<4;nt++){
            int dh[4]={0,0,0,0}, dl[4]={0,0,0,0};
            #pragma unroll
            for(int kc=0;kc<2;kc++){
                mma_s8s8(dh, a[kc], bhi[nt][kc]);
                mma_s8u8(dl, a[kc], blo[nt][kc]);
            }
            int col = vbase + nt*8 + 2*tg;
            float2 v0, v1;
            v0.x = __fmul_rn((float)(dh[0]*256+dl[0]), 1.220703125e-4f);
            v0.y = __fmul_rn((float)(dh[1]*256+dl[1]), 1.220703125e-4f);
            v1.x = __fmul_rn((float)(dh[2]*256+dl[2]), 1.220703125e-4f);
            v1.y = __fmul_rn((float)(dh[3]*256+dl[3]), 1.220703125e-4f);
            *(float2*)(out + (size_t)row0*VOCAB + col)     = v0;
            *(float2*)(out + (size_t)(row0+8)*VOCAB + col) = v1;
        }
    }
}

// ---------------- launch ----------------
extern "C" void kernel_launch(void* const* d_in, const int* in_sizes, int n_in,
                              void* d_out, int out_size){
    const int*   tokens  = (const int*)  d_in[0];
    const float* tok_emb = (const float*)d_in[1];
    const float* pos_emb = (const float*)d_in[2];
    const float* attn_nw = (const float*)d_in[3];
    const float* qw      = (const float*)d_in[4];
    const float* kw      = (const float*)d_in[5];
    const float* vw      = (const float*)d_in[6];
    const float* ow      = (const float*)d_in[7];
    const float* ff_nw   = (const float*)d_in[8];
    const float* up      = (const float*)d_in[9];
    const float* dn      = (const float*)d_in[10];
    const float* fin_nw  = (const float*)d_in[11];
    float* out = (float*)d_out;

    cudaFuncSetAttribute(attn_fused_kernel,
                         cudaFuncAttributeMaxDynamicSharedMemorySize, ATTN_SMEM);

    quant_weights<<<24,256>>>(qw,kw,vw,ow,up,dn);
    prep_emb<<<(VOCAB*D+255)/256,256>>>(tok_emb, attn_nw, ff_nw, fin_nw);
    embed_kernel<<<(BT*D+255)/256,256>>>(tokens, tok_emb, pos_emb);

    for(int l=0;l<NL;l++){
        qkv_norm_kernel<<<BT/4,192>>>(l);
        attn_fused_kernel<<<dim3(T/8, BATCH*H),256,ATTN_SMEM>>>();
        ffn_fused_kernel<<<BT,256>>>(l);
    }
    rmsnorm_final_kernel<<<BT/8,256>>>();
    logits_mma_kernel<<<dim3(VOCAB/256, BT/64),256>>>(out);
}

// round 7
// speedup vs baseline: 19.4960x; 2.7065x over previous
#include <cuda_runtime.h>
#include <cstdint>

#define BATCH 4
#define T 1024
#define D 64
#define H 2
#define HD 32
#define DFF 256
#define NL 4
#define VOCAB 8192
#define BT (BATCH*T)

// ---------------- device scratch (no allocs allowed) ----------------
__device__ __align__(16) int8_t  g_x[BT*D];
__device__ __align__(16) int8_t  g_h[BT*D];
__device__ __align__(16) int8_t  g_q[BT*D];
__device__ __align__(16) int8_t  g_k[BT*D];
__device__ __align__(16) int8_t  g_v[BT*D];
__device__ __align__(16) int8_t  g_a[BT*D];
__device__ __align__(16) int8_t  g_wq[NL*D*D], g_wk[NL*D*D], g_wv[NL*D*D], g_wo[NL*D*D];
__device__ __align__(16) int8_t  g_wup[NL*DFF*D], g_wdn[NL*D*DFF];
__device__ __align__(16) int     g_gattn[NL*D], g_gff[NL*D], g_gfin[D];
__device__ __align__(16) int8_t  g_ehi[VOCAB*D];
__device__ __align__(16) uint8_t g_elo[VOCAB*D];

// ---------------- helpers ----------------
__device__ __forceinline__ int wrap8(int v){ return (int)(signed char)(v & 0xff); }
__device__ __forceinline__ int clampi(int v,int lo,int hi){ return min(max(v,lo),hi); }
__device__ __forceinline__ int gammaq(float w){
    float c = fminf(fmaxf(w,-2.f),2.f);
    float r = rintf(__fmul_rn(c,1024.f));
    return clampi((int)r,-32768,32767);
}
__device__ __forceinline__ void rms_pair(int x0,int x1,int g0,int g1,int& y0,int& y1){
    int ss = x0*x0 + x1*x1;
    #pragma unroll
    for(int o=16;o>0;o>>=1) ss += __shfl_xor_sync(0xffffffffu, ss, o);
    int mean_sq = ss >> 6;
    int lut = min(mean_sq >> 6, 255);
    float bc = (float)(lut*64 + 32);
    int inv = clampi((int)rintf(__fdiv_rn(16384.f, __fsqrt_rn(bc))), 0, 16383);
    int p0 = (x0*inv) >> 8, p1 = (x1*inv) >> 8;
    y0 = clampi((int)floorf(__fmul_rn(__fmul_rn((float)p0,(float)g0), 0.0009765625f)),-128,127);
    y1 = clampi((int)floorf(__fmul_rn(__fmul_rn((float)p1,(float)g1), 0.0009765625f)),-128,127);
}
// m16n8k32 int8 MMA
__device__ __forceinline__ void mma_s8s8(int* d, const int* a, const int* b){
    asm("mma.sync.aligned.m16n8k32.row.col.s32.s8.s8.s32 "
        "{%0,%1,%2,%3},{%4,%5,%6,%7},{%8,%9},{%0,%1,%2,%3};"
        : "+r"(d[0]),"+r"(d[1]),"+r"(d[2]),"+r"(d[3])
        : "r"(a[0]),"r"(a[1]),"r"(a[2]),"r"(a[3]),"r"(b[0]),"r"(b[1]));
}
__device__ __forceinline__ void mma_s8u8(int* d, const int* a, const int* b){
    asm("mma.sync.aligned.m16n8k32.row.col.s32.s8.u8.s32 "
        "{%0,%1,%2,%3},{%4,%5,%6,%7},{%8,%9},{%0,%1,%2,%3};"
        : "+r"(d[0]),"+r"(d[1]),"+r"(d[2]),"+r"(d[3])
        : "r"(a[0]),"r"(a[1]),"r"(a[2]),"r"(a[3]),"r"(b[0]),"r"(b[1]));
}
__device__ __forceinline__ void mma_u8s8(int* d, const unsigned* a, const int* b){
    asm("mma.sync.aligned.m16n8k32.row.col.s32.u8.s8.s32 "
        "{%0,%1,%2,%3},{%4,%5,%6,%7},{%8,%9},{%0,%1,%2,%3};"
        : "+r"(d[0]),"+r"(d[1]),"+r"(d[2]),"+r"(d[3])
        : "r"(a[0]),"r"(a[1]),"r"(a[2]),"r"(a[3]),"r"(b[0]),"r"(b[1]));
}

// ---------------- merged prep: weight ternarization + emb/gamma quant ----------------
__global__ void prep_all(const float* qw, const float* kw, const float* vw,
                         const float* ow, const float* up, const float* dn,
                         const float* tok_emb, const float* attn_nw,
                         const float* ff_nw, const float* fin_nw){
    int m = blockIdx.x;
    if(m < 24){
        const float* src; int8_t* dst; int n;
        if(m < 16){
            int l = m >> 2, wsel = m & 3; n = D*D;
            const float* bases[4] = {qw,kw,vw,ow};
            int8_t* dsts[4] = {g_wq,g_wk,g_wv,g_wo};
            src = bases[wsel] + l*n; dst = dsts[wsel] + l*n;
        } else if(m < 20){ int l=m-16; n=DFF*D; src=up+l*n; dst=g_wup+l*n; }
        else             { int l=m-20; n=D*DFF; src=dn+l*n; dst=g_wdn+l*n; }

        __shared__ float red[256];
        float s = 0.f;
        for(int i=threadIdx.x;i<n;i+=256) s += fabsf(src[i]);
        red[threadIdx.x]=s; __syncthreads();
        for(int o=128;o>0;o>>=1){ if(threadIdx.x<o) red[threadIdx.x]+=red[threadIdx.x+o]; __syncthreads(); }
        float scale = fmaxf(__fdiv_rn(red[0], (float)n), 1e-5f);
        for(int i=threadIdx.x;i<n;i+=256){
            float t = rintf(__fdiv_rn(src[i], scale));
            t = fminf(fmaxf(t,-1.f),1.f);
            dst[i] = (int8_t)(int)t;
        }
        return;
    }
    int i = (m-24)*256 + threadIdx.x;
    if(i < VOCAB*D){
        float r = rintf(__fmul_rn(tok_emb[i],1024.f));
        int q = clampi((int)r,-32768,32767);
        g_ehi[i] = (int8_t)(q >> 8);
        g_elo[i] = (uint8_t)(q & 0xff);
    }
    if(m == 24){
        int t=threadIdx.x;
        for(int j=t;j<NL*D;j+=256){
            g_gattn[j] = gammaq(attn_nw[j]);
            g_gff[j]   = gammaq(ff_nw[j]);
        }
        if(t<D) g_gfin[t] = gammaq(fin_nw[t]);
    }
}

// ---------------- token+pos embedding ----------------
__global__ void embed_kernel(const int* tokens, const float* tok_emb, const float* pos_emb){
    int i = blockIdx.x*256 + threadIdx.x;
    if(i >= BT*D) return;
    int bt = i >> 6, d = i & 63;
    int t = bt & (T-1);
    int tok = tokens[bt];
    int tq = clampi((int)rintf(__fmul_rn(tok_emb[tok*D+d],1024.f)),-32768,32767);
    int pq = clampi((int)rintf(__fmul_rn(pos_emb[t*D+d],1024.f)),-32768,32767);
    g_x[i] = (int8_t)wrap8((tq+pq) >> 3);
}

// ---------------- final rmsnorm (x -> g_h), one warp per row ----------------
__global__ void rmsnorm_final_kernel(){
    int row  = (blockIdx.x*blockDim.x + threadIdx.x) >> 5;
    int lane = threadIdx.x & 31;
    if(row >= BT) return;
    const int8_t* r = g_x + row*D;
    int x0 = r[lane*2], x1 = r[lane*2+1];
    int y0,y1;
    rms_pair(x0,x1,g_gfin[lane*2],g_gfin[lane*2+1],y0,y1);
    g_h[row*D+lane*2]   = (int8_t)y0;
    g_h[row*D+lane*2+1] = (int8_t)y1;
}

// ---------------- fused rmsnorm + QKV via MMA: 16 tokens per block ----------------
__global__ __launch_bounds__(256) void qkv_norm_kernel(int layer){
    __shared__ uint8_t shb[16*68];
    int tid = threadIdx.x, warp = tid>>5, lane = tid&31;
    int g = lane>>2, tg = lane&3;
    int bt0 = blockIdx.x*16;
    const int* gm = g_gattn + layer*D;
    // rmsnorm: warp handles tokens 2*warp, 2*warp+1
    #pragma unroll
    for(int t=0;t<2;t++){
        int tok = 2*warp + t;
        const int8_t* xr = g_x + (bt0+tok)*D;
        int x0 = xr[2*lane], x1 = xr[2*lane+1];
        int y0,y1;
        rms_pair(x0,x1,gm[2*lane],gm[2*lane+1],y0,y1);
        shb[tok*68 + 2*lane]   = (uint8_t)(y0 & 0xff);
        shb[tok*68 + 2*lane+1] = (uint8_t)(y1 & 0xff);
    }
    __syncthreads();
    // A fragments (16 tokens x K=64), pitch 17 ints
    const int* shi = (const int*)shb;
    int a[2][4];
    #pragma unroll
    for(int kc=0;kc<2;kc++){
        a[kc][0] = shi[g*17     + kc*8 + tg];
        a[kc][1] = shi[(g+8)*17 + kc*8 + tg];
        a[kc][2] = shi[g*17     + kc*8 + 4 + tg];
        a[kc][3] = shi[(g+8)*17 + kc*8 + 4 + tg];
    }
    const int* wq = (const int*)(g_wq + layer*D*D);
    const int* wk = (const int*)(g_wk + layer*D*D);
    const int* wv = (const int*)(g_wv + layer*D*D);
    #pragma unroll
    for(int nt=0;nt<3;nt++){
        const int* wb = (nt==0) ? wq : (nt==1 ? wk : wv);
        int8_t* dst   = (nt==0) ? g_q : (nt==1 ? g_k : g_v);
        int c = warp*8 + g;            // B-frag col within 0..63
        int d[4] = {0,0,0,0};
        #pragma unroll
        for(int kc=0;kc<2;kc++){
            int b[2] = { wb[c*16 + kc*8 + tg], wb[c*16 + kc*8 + 4 + tg] };
            mma_s8s8(d, a[kc], b);
        }
        int o0 = warp*8 + 2*tg;
        int v0 = clampi(d[0]>>6,-128,127) & 0xff, v1 = clampi(d[1]>>6,-128,127) & 0xff;
        int v2 = clampi(d[2]>>6,-128,127) & 0xff, v3 = clampi(d[3]>>6,-128,127) & 0xff;
        *(uint16_t*)(dst + (bt0+g)*64   + o0) = (uint16_t)(v0 | (v1<<8));
        *(uint16_t*)(dst + (bt0+g+8)*64 + o0) = (uint16_t)(v2 | (v3<<8));
    }
}

// ---------------- fused attention: scores + LUT softmax + MMA AV ----------------
#define SK_WORDS   (T*8)
#define SVT_PITCH  33
#define SVT_WORDS  ((T/4)*SVT_PITCH)
#define SP_PITCH   1040
#define SP_BYTES   (8*SP_PITCH)
#define ATTN_SMEM  ((SK_WORDS+SVT_WORDS)*4 + SP_BYTES + 256*4)
__device__ __forceinline__ int ksw(int k,int w){ return k*8 + (w ^ ((k>>2)&7)); }

__global__ __launch_bounds__(256) void attn_fused_kernel(){
    extern __shared__ unsigned dyn[];
    unsigned* sK  = dyn;
    unsigned* sVT = dyn + SK_WORDS;
    uint8_t*  sP  = (uint8_t*)(dyn + SK_WORDS + SVT_WORDS);
    int*      sred = (int*)(sP + SP_BYTES);
    int bh = blockIdx.y; int b = bh>>1, h = bh&1;
    int warp = threadIdx.x>>5, lane = threadIdx.x&31;
    int g = lane>>2, tg = lane&3;

    int jmaxb = (blockIdx.x*8+7)>>5;
    int KN = (jmaxb+1)*32;

    const unsigned* kb = (const unsigned*)g_k + (b*T)*16 + h*8;
    const unsigned* vb = (const unsigned*)g_v + (b*T)*16 + h*8;
    uint8_t* svb = (uint8_t*)sVT;
    for(int idx=threadIdx.x; idx<KN*8; idx+=256){
        int k = idx>>3, w = idx&7;
        sK[ksw(k,w)] = kb[k*16+w];
        unsigned u = vb[k*16+w];
        int c = k>>2, r = k&3, d0 = w*4;
        svb[c*(SVT_PITCH*4) + (d0+0)*4 + r] = (uint8_t)( u        & 0xff);
        svb[c*(SVT_PITCH*4) + (d0+1)*4 + r] = (uint8_t)((u >> 8)  & 0xff);
        svb[c*(SVT_PITCH*4) + (d0+2)*4 + r] = (uint8_t)((u >> 16) & 0xff);
        svb[c*(SVT_PITCH*4) + (d0+3)*4 + r] = (uint8_t)((u >> 24) & 0xff);
    }
    __syncthreads();

    int q = blockIdx.x*8 + warp;
    const unsigned* qv = (const unsigned*)g_q + (b*T+q)*16 + h*8;
    unsigned qr[8];
    #pragma unroll
    for(int w=0;w<8;w++) qr[w] = qv[w];

    const int NEG = (int)0x80000000;
    int sc[32];
    int mx = NEG;
    #pragma unroll
    for(int j=0;j<32;j++){
        sc[j] = NEG;
        if(j > jmaxb) break;
        int k = j*32 + lane;
        if(k <= q){
            int acc = 0;
            #pragma unroll
            for(int w=0;w<8;w++) acc = __dp4a((int)qr[w], (int)sK[ksw(k,w)], acc);
            float p = __int2float_rn(acc*45);
            int s = (int)floorf(__fmul_rn(p, 0.00390625f));
            sc[j] = s; mx = max(mx, s);
        }
    }
    #pragma unroll
    for(int o=16;o>0;o>>=1) mx = max(mx, __shfl_xor_sync(0xffffffffu, mx, o));

    int sh_l = lane - 24;
    int ea_l = (sh_l>=-3) ? 256 + sh_l*64
             : (sh_l>=-8) ? 64 + (sh_l+3)*11
             : sh_l + 24;
    if(lane > 24) ea_l = 0;

    int su = 0;
    #pragma unroll
    for(int j=0;j<32;j++){
        if(j > jmaxb) break;
        bool valid = (sc[j] != NEG);
        int idx = valid ? (sc[j] - mx + 24) : -1;
        int idxc = clampi(idx, 0, 31);
        int ea = __shfl_sync(0xffffffffu, ea_l, idxc);
        if(!(valid && idx >= 0)) ea = 0;
        su += ea;
        sc[j] = (valid && idx >= 0) ? idx : 32;
    }
    #pragma unroll
    for(int o=16;o>0;o>>=1) su += __shfl_xor_sync(0xffffffffu, su, o);
    float sf = (float)max(su, 1);

    int p_l = 0;
    if(ea_l > 0)
        p_l = clampi((int)rintf(__fmul_rn(__fdiv_rn((float)ea_l, sf), 255.f)), 0, 255);

    uint8_t* prow = sP + warp*SP_PITCH;
    #pragma unroll
    for(int j=0;j<32;j++){
        if(j > jmaxb) break;
        int idx = sc[j];
        int p = __shfl_sync(0xffffffffu, p_l, idx & 31);
        if(idx >= 32) p = 0;
        prow[j*32+lane] = (uint8_t)p;
    }
    __syncthreads();

    int nt = warp & 3, half = warp >> 2;
    int dim = nt*8 + g;
    int dacc[4] = {0,0,0,0};
    for(int c32 = half; c32 <= jmaxb; c32 += 2){
        const uint8_t* pr = sP + g*SP_PITCH + c32*32;
        unsigned A[4];
        A[0] = *(const unsigned*)(pr + tg*4);
        A[1] = A[0];
        A[2] = *(const unsigned*)(pr + 16 + tg*4);
        A[3] = A[2];
        int Bv[2];
        Bv[0] = (int)sVT[(c32*8 + tg)*SVT_PITCH + dim];
        Bv[1] = (int)sVT[(c32*8 + 4 + tg)*SVT_PITCH + dim];
        mma_u8s8(dacc, A, Bv);
    }
    if(half == 1){
        sred[nt*64 + g*8 + 2*tg]     = dacc[0];
        sred[nt*64 + g*8 + 2*tg + 1] = dacc[1];
    }
    __syncthreads();
    if(half == 0){
        int v0 = dacc[0] + sred[nt*64 + g*8 + 2*tg];
        int v1 = dacc[1] + sred[nt*64 + g*8 + 2*tg + 1];
        int qq = blockIdx.x*8 + g;
        int o0 = wrap8(v0>>8) & 0xff, o1 = wrap8(v1>>8) & 0xff;
        *(uint16_t*)(g_a + (b*T+qq)*64 + h*32 + nt*8 + 2*tg) = (uint16_t)(o0 | (o1<<8));
    }
}

// ---------------- fused oproj+residual+rmsnorm+FFN+residual via MMA: 16 tokens ----------------
__global__ __launch_bounds__(256) void ffn_fused_kernel(int layer){
    __shared__ int      sa[16*17];
    __shared__ uint8_t  sxb[16*64];
    __shared__ uint8_t  shb[16*68];
    __shared__ uint8_t  sub[16*260];
    int tid = threadIdx.x, warp = tid>>5, lane = tid&31;
    int g = lane>>2, tg = lane&3;
    int bt0 = blockIdx.x*16;

    {   // stage g_a (16 tokens x 16 words)
        int tok = tid>>4, i = tid&15;
        sa[tok*17+i] = ((const int*)g_a)[(bt0+tok)*16 + i];
    }
    __syncthreads();

    // ---- oproj MMA: warp -> 8-col tile ----
    {
        int a[2][4];
        #pragma unroll
        for(int kc=0;kc<2;kc++){
            a[kc][0] = sa[g*17     + kc*8 + tg];
            a[kc][1] = sa[(g+8)*17 + kc*8 + tg];
            a[kc][2] = sa[g*17     + kc*8 + 4 + tg];
            a[kc][3] = sa[(g+8)*17 + kc*8 + 4 + tg];
        }
        const int* wo = (const int*)(g_wo + layer*D*D);
        int c = warp*8 + g;
        int d[4] = {0,0,0,0};
        #pragma unroll
        for(int kc=0;kc<2;kc++){
            int b[2] = { wo[c*16 + kc*8 + tg], wo[c*16 + kc*8 + 4 + tg] };
            mma_s8s8(d, a[kc], b);
        }
        int o0 = warp*8 + 2*tg;
        int r0 = clampi(d[0]>>6,-128,127), r1 = clampi(d[1]>>6,-128,127);
        int r2 = clampi(d[2]>>6,-128,127), r3 = clampi(d[3]>>6,-128,127);
        sxb[g*64 + o0]       = (uint8_t)(wrap8((int)g_x[(bt0+g)*64 + o0]     + r0) & 0xff);
        sxb[g*64 + o0+1]     = (uint8_t)(wrap8((int)g_x[(bt0+g)*64 + o0+1]   + r1) & 0xff);
        sxb[(g+8)*64 + o0]   = (uint8_t)(wrap8((int)g_x[(bt0+g+8)*64 + o0]   + r2) & 0xff);
        sxb[(g+8)*64 + o0+1] = (uint8_t)(wrap8((int)g_x[(bt0+g+8)*64 + o0+1] + r3) & 0xff);
    }
    __syncthreads();

    // ---- rmsnorm: warp handles tokens 2w, 2w+1 ----
    {
        const int* gm = g_gff + layer*D;
        #pragma unroll
        for(int t=0;t<2;t++){
            int tok = 2*warp + t;
            int x0 = (int)(int8_t)sxb[tok*64 + 2*lane];
            int x1 = (int)(int8_t)sxb[tok*64 + 2*lane+1];
            int y0,y1;
            rms_pair(x0,x1,gm[2*lane],gm[2*lane+1],y0,y1);
            shb[tok*68 + 2*lane]   = (uint8_t)(y0 & 0xff);
            shb[tok*68 + 2*lane+1] = (uint8_t)(y1 & 0xff);
        }
    }
    __syncthreads();

    // ---- up + relu MMA: warp -> 4 x 8-col tiles (N=256) ----
    {
        const int* shi = (const int*)shb;
        int a[2][4];
        #pragma unroll
        for(int kc=0;kc<2;kc++){
            a[kc][0] = shi[g*17     + kc*8 + tg];
            a[kc][1] = shi[(g+8)*17 + kc*8 + tg];
            a[kc][2] = shi[g*17     + kc*8 + 4 + tg];
            a[kc][3] = shi[(g+8)*17 + kc*8 + 4 + tg];
        }
        const int* wu = (const int*)(g_wup + layer*DFF*D);
        #pragma unroll
        for(int nt=0;nt<4;nt++){
            int colb = warp*32 + nt*8;
            int c = colb + g;
            int d[4] = {0,0,0,0};
            #pragma unroll
            for(int kc=0;kc<2;kc++){
                int b[2] = { wu[c*16 + kc*8 + tg], wu[c*16 + kc*8 + 4 + tg] };
                mma_s8s8(d, a[kc], b);
            }
            int c0 = colb + 2*tg;
            int u0 = max(clampi(d[0]>>6,-128,127),0), u1 = max(clampi(d[1]>>6,-128,127),0);
            int u2 = max(clampi(d[2]>>6,-128,127),0), u3 = max(clampi(d[3]>>6,-128,127),0);
            sub[g*260 + c0]       = (uint8_t)u0;
            sub[g*260 + c0+1]     = (uint8_t)u1;
            sub[(g+8)*260 + c0]   = (uint8_t)u2;
            sub[(g+8)*260 + c0+1] = (uint8_t)u3;
        }
    }
    __syncthreads();

    // ---- down MMA (K=256): warp -> 8-col tile ----
    {
        const int* sui = (const int*)sub;
        const int* wd = (const int*)(g_wdn + layer*D*DFF);
        int c = warp*8 + g;
        int d[4] = {0,0,0,0};
        #pragma unroll
        for(int kc=0;kc<8;kc++){
            int a[4];
            a[0] = sui[g*65     + kc*8 + tg];
            a[1] = sui[(g+8)*65 + kc*8 + tg];
            a[2] = sui[g*65     + kc*8 + 4 + tg];
            a[3] = sui[(g+8)*65 + kc*8 + 4 + tg];
            int b[2] = { wd[c*64 + kc*8 + tg], wd[c*64 + kc*8 + 4 + tg] };
            mma_s8s8(d, a, b);
        }
        int o0 = warp*8 + 2*tg;
        int r0 = clampi(d[0]>>6,-128,127), r1 = clampi(d[1]>>6,-128,127);
        int r2 = clampi(d[2]>>6,-128,127), r3 = clampi(d[3]>>6,-128,127);
        g_x[(bt0+g)*64 + o0]     = (int8_t)wrap8((int)(int8_t)sxb[g*64 + o0]       + r0);
        g_x[(bt0+g)*64 + o0+1]   = (int8_t)wrap8((int)(int8_t)sxb[g*64 + o0+1]     + r1);
        g_x[(bt0+g+8)*64 + o0]   = (int8_t)wrap8((int)(int8_t)sxb[(g+8)*64 + o0]   + r2);
        g_x[(bt0+g+8)*64 + o0+1] = (int8_t)wrap8((int)(int8_t)sxb[(g+8)*64 + o0+1] + r3);
    }
}

// ---------------- logits via IMMA: warp = 64 tokens x 32 vocab ----------------
__global__ __launch_bounds__(256) void logits_mma_kernel(float* __restrict__ out){
    int warp = threadIdx.x>>5, lane = threadIdx.x&31;
    int g = lane>>2, tg = lane&3;
    int vbase = blockIdx.x*256 + warp*32;
    int mbase = blockIdx.y*64;

    int bhi[4][2][2], blo[4][2][2];
    #pragma unroll
    for(int nt=0;nt<4;nt++){
        int col = vbase + nt*8 + g;
        const int8_t*  eh = g_ehi + col*64;
        const uint8_t* el = g_elo + col*64;
        #pragma unroll
        for(int kc=0;kc<2;kc++){
            bhi[nt][kc][0] = *(const int*)(eh + kc*32 + tg*4);
            bhi[nt][kc][1] = *(const int*)(eh + kc*32 + 16 + tg*4);
            blo[nt][kc][0] = *(const int*)(el + kc*32 + tg*4);
            blo[nt][kc][1] = *(const int*)(el + kc*32 + 16 + tg*4);
        }
    }
    #pragma unroll
    for(int mt=0;mt<4;mt++){
        int row0 = mbase + mt*16 + g;
        const int8_t* h0 = g_h + row0*64;
        const int8_t* h8 = g_h + (row0+8)*64;
        int a[2][4];
        #pragma unroll
        for(int kc=0;kc<2;kc++){
            a[kc][0] = *(const int*)(h0 + kc*32 + tg*4);
            a[kc][1] = *(const int*)(h8 + kc*32 + tg*4);
            a[kc][2] = *(const int*)(h0 + kc*32 + 16 + tg*4);
            a[kc][3] = *(const int*)(h8 + kc*32 + 16 + tg*4);
        }
        #pragma unroll
        for(int nt=0;nt<4;nt++){
            int dh[4]={0,0,0,0}, dl[4]={0,0,0,0};
            #pragma unroll
            for(int kc=0;kc<2;kc++){
                mma_s8s8(dh, a[kc], bhi[nt][kc]);
                mma_s8u8(dl, a[kc], blo[nt][kc]);
            }
            int col = vbase + nt*8 + 2*tg;
            float2 v0, v1;
            v0.x = __fmul_rn((float)(dh[0]*256+dl[0]), 1.220703125e-4f);
            v0.y = __fmul_rn((float)(dh[1]*256+dl[1]), 1.220703125e-4f);
            v1.x = __fmul_rn((float)(dh[2]*256+dl[2]), 1.220703125e-4f);
            v1.y = __fmul_rn((float)(dh[3]*256+dl[3]), 1.220703125e-4f);
            *(float2*)(out + (size_t)row0*VOCAB + col)     = v0;
            *(float2*)(out + (size_t)(row0+8)*VOCAB + col) = v1;
        }
    }
}

// ---------------- launch ----------------
extern "C" void kernel_launch(void* const* d_in, const int* in_sizes, int n_in,
                              void* d_out, int out_size){
    const int*   tokens  = (const int*)  d_in[0];
    const float* tok_emb = (const float*)d_in[1];
    const float* pos_emb = (const float*)d_in[2];
    const float* attn_nw = (const float*)d_in[3];
    const float* qw      = (const float*)d_in[4];
    const float* kw      = (const float*)d_in[5];
    const float* vw      = (const float*)d_in[6];
    const float* ow      = (const float*)d_in[7];
    const float* ff_nw   = (const float*)d_in[8];
    const float* up      = (const float*)d_in[9];
    const float* dn      = (const float*)d_in[10];
    const float* fin_nw  = (const float*)d_in[11];
    float* out = (float*)d_out;

    cudaFuncSetAttribute(attn_fused_kernel,
                         cudaFuncAttributeMaxDynamicSharedMemorySize, ATTN_SMEM);

    prep_all<<<24 + (VOCAB*D+255)/256, 256>>>(qw,kw,vw,ow,up,dn,
                                              tok_emb, attn_nw, ff_nw, fin_nw);
    embed_kernel<<<(BT*D+255)/256,256>>>(tokens, tok_emb, pos_emb);

    for(int l=0;l<NL;l++){
        qkv_norm_kernel<<<BT/16,256>>>(l);
        attn_fused_kernel<<<dim3(T/8, BATCH*H),256,ATTN_SMEM>>>();
        ffn_fused_kernel<<<BT/16,256>>>(l);
    }
    rmsnorm_final_kernel<<<BT/8,256>>>();
    logits_mma_kernel<<<dim3(VOCAB/256, BT/64),256>>>(out);
}